// round 11
// baseline (speedup 1.0000x reference)
#include <cuda_runtime.h>
#include <cuda_bf16.h>
#include <cstdint>

#define N_NODES 50000
#define HID 128
#define EF 64

// ---------------------------------------------------------------------------
// Scratch (device globals — allocation-free per harness rules)
__device__ float g_P   [(size_t)N_NODES * HID];   // node_feat@W1_top+b1
__device__ float g_P3  [(size_t)N_NODES * HID];   // node_feat@W3_top+b3
__device__ float g_sums[(size_t)N_NODES * HID];   // scatter-add of relu-h
__device__ float g_cnt [N_NODES];
__device__ float g_W23 [128 * 128];               // W2 @ W3_bot (fp32)
__device__ float g_b23 [128];                     // b2 @ W3_bot
// bf16 hi/lo weight images, [N][K] K-major 128B rows, SW128-swizzled.
// [0,16K) B1hi | [16K,32K) B1lo | then 4 node weights x 64KB each.
// widx: 0=W1_top 1=W3_top 2=W23 3=W4
__device__ __align__(16) unsigned char g_WB[32768 + 4 * 65536];

__device__ __forceinline__ uint32_t smem_u32(const void* p) {
    uint32_t a;
    asm("{ .reg .u64 t; cvta.to.shared.u64 t, %1; cvt.u32.u64 %0, t; }"
        : "=r"(a) : "l"(p));
    return a;
}
__device__ __forceinline__ uint32_t swz(uint32_t b) { return b ^ ((b >> 3) & 0x70); }

__device__ __forceinline__ void ldsm_x4(uint32_t* r, uint32_t addr) {
    asm volatile("ldmatrix.sync.aligned.m8n8.x4.shared.b16 {%0,%1,%2,%3}, [%4];"
                 : "=r"(r[0]), "=r"(r[1]), "=r"(r[2]), "=r"(r[3]) : "r"(addr));
}
__device__ __forceinline__ void mma_bf16(float* d, const uint32_t* a, const uint32_t* b) {
    asm volatile("mma.sync.aligned.m16n8k16.row.col.f32.bf16.bf16.f32 "
                 "{%0,%1,%2,%3}, {%4,%5,%6,%7}, {%8,%9}, {%0,%1,%2,%3};"
                 : "+f"(d[0]), "+f"(d[1]), "+f"(d[2]), "+f"(d[3])
                 : "r"(a[0]), "r"(a[1]), "r"(a[2]), "r"(a[3]), "r"(b[0]), "r"(b[1]));
}
__device__ __forceinline__ uint32_t pack_bf16x2(float x, float y) {
    __nv_bfloat162 p = {__float2bfloat16(x), __float2bfloat16(y)};
    return *(uint32_t*)&p;
}
__device__ __forceinline__ void split2(float x, float y, uint32_t& hi, uint32_t& lo) {
    __nv_bfloat16 hx = __float2bfloat16(x), hy = __float2bfloat16(y);
    __nv_bfloat162 ph = {hx, hy};
    hi = *(uint32_t*)&ph;
    lo = pack_bf16x2(x - __bfloat162float(hx), y - __bfloat162float(hy));
}
__device__ __forceinline__ void split8(float4 v0, float4 v1, uint4& hi, uint4& lo) {
    split2(v0.x, v0.y, hi.x, lo.x);
    split2(v0.z, v0.w, hi.y, lo.y);
    split2(v1.x, v1.y, hi.z, lo.z);
    split2(v1.z, v1.w, hi.w, lo.w);
}

// Shared K=128 bf16x3 GEMM core with x4 B-operand ldmatrix (256-thr kernels).
__device__ __forceinline__ void gemm128_core(
    uint32_t smb, uint32_t aoff, uint32_t woff, int lid,
    int arow, int akof, float acc[16][4]) {
    const int ntoff = lid >> 4;
    const int brow = lid & 7;
    const int bkof = ((lid >> 3) & 1) << 4;
    #pragma unroll
    for (int kt = 0; kt < 8; kt++) {
        const int chunk = (kt >> 2) * 16384;
        const int kb = (kt & 3) * 32;
        uint32_t ahi[4], alo[4];
        ldsm_x4(ahi, smb + aoff + chunk + swz(arow * 128 + kb + akof));
        ldsm_x4(alo, smb + aoff + 32768 + chunk + swz(arow * 128 + kb + akof));
        #pragma unroll
        for (int nt = 0; nt < 16; nt += 2) {
            uint32_t bo = swz(((nt + ntoff) * 8 + brow) * 128 + kb + bkof);
            uint32_t bh[4], bl[4];
            ldsm_x4(bh, smb + woff + chunk + bo);
            ldsm_x4(bl, smb + woff + 32768 + chunk + bo);
            mma_bf16(acc[nt],     ahi, bh);
            mma_bf16(acc[nt],     ahi, bl);
            mma_bf16(acc[nt],     alo, bh);
            mma_bf16(acc[nt + 1], ahi, bh + 2);
            mma_bf16(acc[nt + 1], ahi, bl + 2);
            mma_bf16(acc[nt + 1], alo, bh + 2);
        }
    }
}

// ---------------------------------------------------------------------------
__global__ void zero_kernel() {
    const size_t total4 = (size_t)N_NODES * HID / 4;
    float4* s = (float4*)g_sums;
    const float4 z = make_float4(0.f, 0.f, 0.f, 0.f);
    for (size_t i = (size_t)blockIdx.x * blockDim.x + threadIdx.x; i < total4;
         i += (size_t)gridDim.x * blockDim.x)
        s[i] = z;
    for (int i = blockIdx.x * blockDim.x + threadIdx.x; i < N_NODES;
         i += gridDim.x * blockDim.x)
        g_cnt[i] = 0.f;
}

// ---------------------------------------------------------------------------
// W23 = W2 @ W3[128:256], b23 = b2 @ W3[128:256]
__global__ void prep1_kernel(const float* __restrict__ W2,
                             const float* __restrict__ W3,
                             const float* __restrict__ b2) {
    __shared__ float srow[128];
    const int r = blockIdx.x;
    const int c = threadIdx.x;
    srow[c] = (r < 128) ? W2[r * 128 + c] : b2[c];
    __syncthreads();
    float acc = 0.f;
    #pragma unroll 4
    for (int k = 0; k < 128; k++)
        acc += srow[k] * W3[(128 + k) * 128 + c];
    if (r < 128) g_W23[r * 128 + c] = acc;
    else         g_b23[c] = acc;
}

// ---------------------------------------------------------------------------
__global__ void prep2_kernel(const float* __restrict__ W1,
                             const float* __restrict__ W3,
                             const float* __restrict__ W4) {
    const int tid = blockIdx.x * blockDim.x + threadIdx.x;
    const int nth = gridDim.x * blockDim.x;
    for (int i = tid; i < 128 * 64; i += nth) {       // edge B1 = W1 rows 128..191
        int n = i >> 6, k = i & 63;
        float v = W1[(128 + k) * 128 + n];
        __nv_bfloat16 h = __float2bfloat16(v);
        __nv_bfloat16 l = __float2bfloat16(v - __bfloat162float(h));
        uint32_t off = swz(n * 128 + k * 2);
        *(__nv_bfloat16*)(g_WB + off)         = h;
        *(__nv_bfloat16*)(g_WB + 16384 + off) = l;
    }
    for (int i = tid; i < 4 * 128 * 128; i += nth) {  // node weights
        int widx = i >> 14, j = i & 16383;
        int n = j >> 7, k = j & 127;
        float v;
        if      (widx == 0) v = W1[k * 128 + n];
        else if (widx == 1) v = W3[k * 128 + n];
        else if (widx == 2) v = g_W23[k * 128 + n];
        else                v = W4[k * 128 + n];
        __nv_bfloat16 h = __float2bfloat16(v);
        __nv_bfloat16 l = __float2bfloat16(v - __bfloat162float(h));
        int c = k >> 6, kk = k & 63;
        uint32_t off = swz(n * 128 + kk * 2);
        unsigned char* base = g_WB + 32768 + widx * 65536;
        *(__nv_bfloat16*)(base + c * 16384 + off)         = h;
        *(__nv_bfloat16*)(base + 32768 + c * 16384 + off) = l;
    }
}

// ---------------------------------------------------------------------------
// pre_both: stage node_feat once; P = nf@W1t + b1; P3 = nf@W3t + b3.
#define PB_W 0
#define PB_A 65536
#define PB_BIAS 131072
#define PB_SMEM (131072 + 1024)

__global__ __launch_bounds__(256, 1)
void pre_both_kernel(const float* __restrict__ A, const float* __restrict__ b1,
                     const float* __restrict__ b3) {
    extern __shared__ char smc[];
    const uint32_t smb = smem_u32(smc);
    const int tid = threadIdx.x;
    const int wid = tid >> 5;
    const int lid = tid & 31;
    float* s_b1 = (float*)(smc + PB_BIAS);
    float* s_b3 = s_b1 + 128;

    {
        const float4* src = (const float4*)(g_WB + 32768);
        float4* dst = (float4*)smc;
        #pragma unroll
        for (int i = 0; i < 16; i++) dst[tid + 256 * i] = src[tid + 256 * i];
    }
    if (tid < 128) { s_b1[tid] = b1[tid]; s_b3[tid] = b3[tid]; }

    const int m0 = blockIdx.x * 128;
    {
        const int r = tid >> 1;
        const int chunk = tid & 1;
        const int gr = m0 + r;
        const bool valid = gr < N_NODES;
        const float* src = A + (size_t)gr * 128 + chunk * 64;
        #pragma unroll
        for (int j = 0; j < 8; j++) {
            float4 v0 = valid ? *(const float4*)(src + j * 8)
                              : make_float4(0.f, 0.f, 0.f, 0.f);
            float4 v1 = valid ? *(const float4*)(src + j * 8 + 4)
                              : make_float4(0.f, 0.f, 0.f, 0.f);
            uint4 hi, lo;
            split8(v0, v1, hi, lo);
            uint32_t off = swz(r * 128 + j * 16);
            *(uint4*)(smc + PB_A + chunk * 16384 + off) = hi;
            *(uint4*)(smc + PB_A + 32768 + chunk * 16384 + off) = lo;
        }
    }
    __syncthreads();

    const int wr0 = wid * 16;
    const int qr = lid >> 2, qc = (lid & 3) * 2;
    const int r0 = wr0 + qr, r1 = r0 + 8;
    const int am = lid >> 3;
    const int arow = wr0 + ((am & 1) << 3) + (lid & 7);
    const int akof = (am >> 1) << 4;
    const int gr0 = m0 + r0, gr1 = m0 + r1;

    float acc[16][4];
    #pragma unroll
    for (int nt = 0; nt < 16; nt++)
        #pragma unroll
        for (int v = 0; v < 4; v++) acc[nt][v] = 0.f;
    gemm128_core(smb, PB_A, PB_W, lid, arow, akof, acc);
    #pragma unroll
    for (int nt = 0; nt < 16; nt++) {
        const int c = nt * 8 + qc;
        if (gr0 < N_NODES)
            *(float2*)(g_P + (size_t)gr0 * 128 + c) = make_float2(
                acc[nt][0] + s_b1[c], acc[nt][1] + s_b1[c + 1]);
        if (gr1 < N_NODES)
            *(float2*)(g_P + (size_t)gr1 * 128 + c) = make_float2(
                acc[nt][2] + s_b1[c], acc[nt][3] + s_b1[c + 1]);
    }
    __syncthreads();
    {
        const float4* src = (const float4*)(g_WB + 32768 + 65536);
        float4* dst = (float4*)smc;
        #pragma unroll
        for (int i = 0; i < 16; i++) dst[tid + 256 * i] = src[tid + 256 * i];
    }
    __syncthreads();
    #pragma unroll
    for (int nt = 0; nt < 16; nt++)
        #pragma unroll
        for (int v = 0; v < 4; v++) acc[nt][v] = 0.f;
    gemm128_core(smb, PB_A, PB_W, lid, arow, akof, acc);
    #pragma unroll
    for (int nt = 0; nt < 16; nt++) {
        const int c = nt * 8 + qc;
        if (gr0 < N_NODES)
            *(float2*)(g_P3 + (size_t)gr0 * 128 + c) = make_float2(
                acc[nt][0] + s_b3[c], acc[nt][1] + s_b3[c + 1]);
        if (gr1 < N_NODES)
            *(float2*)(g_P3 + (size_t)gr1 * 128 + c) = make_float2(
                acc[nt][2] + s_b3[c], acc[nt][3] + s_b3[c + 1]);
    }
}

// ---------------------------------------------------------------------------
// node_fused: mean = sums/max(cnt,1); T = relu(P3 + mean@W23 + flag*b23);
// out = T@W4 + b4.
__global__ __launch_bounds__(256, 1)
void node_fused_kernel(const float* __restrict__ b4, float* __restrict__ out) {
    extern __shared__ char smc[];
    const uint32_t smb = smem_u32(smc);
    const int tid = threadIdx.x;
    const int wid = tid >> 5;
    const int lid = tid & 31;
    float* s_b23 = (float*)(smc + PB_BIAS);
    float* s_b4  = s_b23 + 128;

    {
        const float4* src = (const float4*)(g_WB + 32768 + 2 * 65536);
        float4* dst = (float4*)smc;
        #pragma unroll
        for (int i = 0; i < 16; i++) dst[tid + 256 * i] = src[tid + 256 * i];
    }
    if (tid < 128) { s_b23[tid] = g_b23[tid]; s_b4[tid] = b4[tid]; }

    const int m0 = blockIdx.x * 128;
    {
        const int r = tid >> 1;
        const int chunk = tid & 1;
        const int gr = m0 + r;
        const bool valid = gr < N_NODES;
        float s = valid ? 1.f / fmaxf(g_cnt[gr], 1.f) : 0.f;
        const float* src = g_sums + (size_t)gr * 128 + chunk * 64;
        #pragma unroll
        for (int j = 0; j < 8; j++) {
            float4 v0 = valid ? *(const float4*)(src + j * 8)
                              : make_float4(0.f, 0.f, 0.f, 0.f);
            float4 v1 = valid ? *(const float4*)(src + j * 8 + 4)
                              : make_float4(0.f, 0.f, 0.f, 0.f);
            v0.x *= s; v0.y *= s; v0.z *= s; v0.w *= s;
            v1.x *= s; v1.y *= s; v1.z *= s; v1.w *= s;
            uint4 hi, lo;
            split8(v0, v1, hi, lo);
            uint32_t off = swz(r * 128 + j * 16);
            *(uint4*)(smc + PB_A + chunk * 16384 + off) = hi;
            *(uint4*)(smc + PB_A + 32768 + chunk * 16384 + off) = lo;
        }
    }
    __syncthreads();

    const int wr0 = wid * 16;
    const int qr = lid >> 2, qc = (lid & 3) * 2;
    const int r0 = wr0 + qr, r1 = r0 + 8;
    const int am = lid >> 3;
    const int arow = wr0 + ((am & 1) << 3) + (lid & 7);
    const int akof = (am >> 1) << 4;
    const int gr0 = m0 + r0, gr1 = m0 + r1;

    float acc[16][4];
    #pragma unroll
    for (int nt = 0; nt < 16; nt++)
        #pragma unroll
        for (int v = 0; v < 4; v++) acc[nt][v] = 0.f;
    gemm128_core(smb, PB_A, PB_W, lid, arow, akof, acc);

    {
        const float f0 = (gr0 < N_NODES && g_cnt[gr0] > 0.f) ? 1.f : 0.f;
        const float f1 = (gr1 < N_NODES && g_cnt[gr1] > 0.f) ? 1.f : 0.f;
        #pragma unroll
        for (int nt = 0; nt < 16; nt++) {
            const int c = nt * 8 + qc;
            float t00 = 0.f, t01 = 0.f, t10 = 0.f, t11 = 0.f;
            if (gr0 < N_NODES) {
                float2 p = *(const float2*)(g_P3 + (size_t)gr0 * 128 + c);
                t00 = fmaxf(p.x + acc[nt][0] + f0 * s_b23[c], 0.f);
                t01 = fmaxf(p.y + acc[nt][1] + f0 * s_b23[c + 1], 0.f);
            }
            if (gr1 < N_NODES) {
                float2 p = *(const float2*)(g_P3 + (size_t)gr1 * 128 + c);
                t10 = fmaxf(p.x + acc[nt][2] + f1 * s_b23[c], 0.f);
                t11 = fmaxf(p.y + acc[nt][3] + f1 * s_b23[c + 1], 0.f);
            }
            uint32_t hi0, lo0, hi1, lo1;
            split2(t00, t01, hi0, lo0);
            split2(t10, t11, hi1, lo1);
            const int chunk = (c >> 6) * 16384;
            const int kk2 = (c & 63) * 2;
            *(uint32_t*)(smc + PB_A + chunk + swz(r0 * 128 + kk2)) = hi0;
            *(uint32_t*)(smc + PB_A + chunk + swz(r1 * 128 + kk2)) = hi1;
            *(uint32_t*)(smc + PB_A + 32768 + chunk + swz(r0 * 128 + kk2)) = lo0;
            *(uint32_t*)(smc + PB_A + 32768 + chunk + swz(r1 * 128 + kk2)) = lo1;
        }
    }
    __syncthreads();
    {
        const float4* src = (const float4*)(g_WB + 32768 + 3 * 65536);
        float4* dst = (float4*)smc;
        #pragma unroll
        for (int i = 0; i < 16; i++) dst[tid + 256 * i] = src[tid + 256 * i];
    }
    __syncthreads();
    #pragma unroll
    for (int nt = 0; nt < 16; nt++)
        #pragma unroll
        for (int v = 0; v < 4; v++) acc[nt][v] = 0.f;
    gemm128_core(smb, PB_A, PB_W, lid, arow, akof, acc);
    #pragma unroll
    for (int nt = 0; nt < 16; nt++) {
        const int c = nt * 8 + qc;
        if (gr0 < N_NODES)
            *(float2*)(out + (size_t)gr0 * 128 + c) = make_float2(
                acc[nt][0] + s_b4[c], acc[nt][1] + s_b4[c + 1]);
        if (gr1 < N_NODES)
            *(float2*)(out + (size_t)gr1 * 128 + c) = make_float2(
                acc[nt][2] + s_b4[c], acc[nt][3] + s_b4[c + 1]);
    }
}

// ---------------------------------------------------------------------------
// Edge kernel: 256 threads, 2 CTAs/SM, 32-edge tiles, WEIGHTS IN REGISTERS.
// 8 warps = 2 row-strips(16) x 4 col-quarters(32). Each warp holds its B1
// fragments (hi+lo, all 4 k-steps) in 64 registers, loaded by ldmatrix ONCE
// before the tile loop -> zero steady-state weight traffic through L1/SMEM.
// Per tile: stage A (double-buffered), GEMM (A-ldsm only), prefetch P,
// epilogue relu(D1 + P[col]) -> float4 RED. One __syncthreads per tile.
// SMEM: [0,16K) B1hi | 16K B1lo | 32K A0hi(4K) A0lo(4K) | 40K A1hi A1lo
//       | 48K idx (2 x 64 ints)
#define SM_B1HI 0
#define SM_B1LO 16384
#define SM_A    32768
#define SM_IDX  49152
#define EDGE_SMEM_BYTES (49152 + 768)
#define EDGE_THREADS 256
#define TILE_E 32

__global__ __launch_bounds__(EDGE_THREADS, 2)
void edge_kernel_mma(const float* __restrict__ ea, const int* __restrict__ eidx,
                     int E, int ntiles) {
    extern __shared__ char smc[];
    const uint32_t smb = smem_u32(smc);
    const int tid = threadIdx.x;
    const int wid = tid >> 5;
    const int lid = tid & 31;

    {   // weights once (32 KB)
        const float4* src = (const float4*)g_WB;
        float4* dst = (float4*)smc;
        for (int i = tid; i < 2048; i += EDGE_THREADS) dst[i] = src[i];
    }
    __syncthreads();

    // MMA lane geometry: 2 row strips x 4 col quarters
    const int rstrip = (wid >> 2) * 16;
    const int cq     = (wid & 3) * 32;
    const int qr = lid >> 2;
    const int r0 = rstrip + qr, r1 = r0 + 8;
    const int am = lid >> 3;
    const int arow = rstrip + ((am & 1) << 3) + (lid & 7);
    const int akof = (am >> 1) << 4;
    const int ntoff = lid >> 4;
    const int brow = lid & 7;
    const int bkof = ((lid >> 3) & 1) << 4;

    // ---- load B1 fragments into registers, once ----
    uint32_t Bh[4][2][4], Bl[4][2][4];
    #pragma unroll
    for (int kt = 0; kt < 4; kt++) {
        const int kb = kt * 32;
        #pragma unroll
        for (int p = 0; p < 2; p++) {
            const int ntg = (cq >> 3) + p * 2 + ntoff;
            uint32_t bo = swz((ntg * 8 + brow) * 128 + kb + bkof);
            ldsm_x4(Bh[kt][p], smb + SM_B1HI + bo);
            ldsm_x4(Bl[kt][p], smb + SM_B1LO + bo);
        }
    }

    // staging lane geometry (8 threads/row, 8 floats each; 32 rows)
    const int st_r = tid >> 3;
    const int st_q = tid & 7;

    // epilogue shuffle geometry
    const int cboff = (lid & 2) ? 4 : 0;
    const bool evenlane = ((lid & 1) == 0);
    const int myrow = evenlane ? r0 : r1;

    // ---- stage helper: 32-edge tile into buffer q ----
    auto stage = [&](int tile, int q) {
        const int e0s = tile * TILE_E;
        int* rowq = (int*)(smc + SM_IDX) + q * 64;
        int* colq = rowq + 32;
        if (tid < 32) {
            int e = e0s + tid;
            rowq[tid] = (e < E) ? eidx[e] : 0;
        } else if (tid < 64) {
            int t = tid - 32, e = e0s + t;
            colq[t] = (e < E) ? eidx[(size_t)E + e] : 0;
        }
        const int e = e0s + st_r;
        const bool valid = e < E;
        const float* src = ea + (size_t)e * EF + st_q * 8;
        const uint32_t abase = (uint32_t)(SM_A + q * 8192);
        float4 v0 = valid ? *(const float4*)(src)
                          : make_float4(0.f, 0.f, 0.f, 0.f);
        float4 v1 = valid ? *(const float4*)(src + 4)
                          : make_float4(0.f, 0.f, 0.f, 0.f);
        uint4 hi, lo;
        split8(v0, v1, hi, lo);
        uint32_t off = swz(st_r * 128 + st_q * 16);
        *(uint4*)(smc + abase + off) = hi;
        *(uint4*)(smc + abase + 4096 + off) = lo;
    };

    if (blockIdx.x < ntiles) stage(blockIdx.x, 0);
    __syncthreads();

    int p = 0;
    for (int tile = blockIdx.x; tile < ntiles; tile += gridDim.x, p ^= 1) {
        const int e0 = tile * TILE_E;
        const int* rowp = (const int*)(smc + SM_IDX) + p * 64;
        const int* colp = rowp + 32;
        const uint32_t aoff = (uint32_t)(SM_A + p * 8192);

        // ---- prefetch this thread's P-row quarter to L1 (overlaps GEMM) ----
        const int srcnode = colp[myrow];
        const float* Pbase = g_P + (size_t)srcnode * 128 + cq;
        asm volatile("prefetch.global.L1 [%0];" :: "l"(Pbase));

        // ---- GEMM1: acc[4][4], B from registers ----
        float acc[4][4];
        #pragma unroll
        for (int nt = 0; nt < 4; nt++)
            #pragma unroll
            for (int v = 0; v < 4; v++) acc[nt][v] = 0.f;
        #pragma unroll
        for (int kt = 0; kt < 4; kt++) {
            const int kb = kt * 32;
            uint32_t ahi[4], alo[4];
            ldsm_x4(ahi, smb + aoff + swz(arow * 128 + kb + akof));
            ldsm_x4(alo, smb + aoff + 4096 + swz(arow * 128 + kb + akof));
            #pragma unroll
            for (int pp = 0; pp < 2; pp++) {
                mma_bf16(acc[2 * pp],     ahi, Bh[kt][pp]);
                mma_bf16(acc[2 * pp],     ahi, Bl[kt][pp]);
                mma_bf16(acc[2 * pp],     alo, Bh[kt][pp]);
                mma_bf16(acc[2 * pp + 1], ahi, Bh[kt][pp] + 2);
                mma_bf16(acc[2 * pp + 1], ahi, Bl[kt][pp] + 2);
                mma_bf16(acc[2 * pp + 1], alo, Bh[kt][pp] + 2);
            }
        }

        // ---- stage NEXT tile into the other buffer (overlaps epilogue) ----
        const int nxt = tile + gridDim.x;
        if (nxt < ntiles) stage(nxt, 1 - p);

        // ---- epilogue: shuffle to float4; h = relu(D1 + P[col]); RED.F32X4
        {
            const bool valid = (e0 + myrow < E);
            const float* Pn = Pbase + cboff;
            float* Sn = g_sums + (size_t)rowp[myrow] * 128 + cq + cboff;
            #pragma unroll
            for (int nt = 0; nt < 4; nt++) {
                float sA = evenlane ? acc[nt][2] : acc[nt][0];
                float sB = evenlane ? acc[nt][3] : acc[nt][1];
                float rA = __shfl_xor_sync(0xFFFFFFFFu, sA, 1);
                float rB = __shfl_xor_sync(0xFFFFFFFFu, sB, 1);
                float4 v = evenlane
                    ? make_float4(acc[nt][0], acc[nt][1], rA, rB)
                    : make_float4(rA, rB, acc[nt][2], acc[nt][3]);
                if (valid) {
                    float4 pv = *(const float4*)(Pn + nt * 8);
                    v.x = fmaxf(v.x + pv.x, 0.f);
                    v.y = fmaxf(v.y + pv.y, 0.f);
                    v.z = fmaxf(v.z + pv.z, 0.f);
                    v.w = fmaxf(v.w + pv.w, 0.f);
                    atomicAdd((float4*)(Sn + nt * 8), v);
                }
            }
        }
        if (tid < 32 && e0 + tid < E) atomicAdd(&g_cnt[rowp[tid]], 1.0f);

        __syncthreads();   // buffer 1-p fully staged; buffer p free to rewrite
    }
}

// ---------------------------------------------------------------------------
extern "C" void kernel_launch(void* const* d_in, const int* in_sizes, int n_in,
                              void* d_out, int out_size) {
    const float* node_feat = (const float*)d_in[0];
    const int*   eidx      = (const int*)d_in[1];   // int32 (JAX x64 disabled)
    const float* ea        = (const float*)d_in[2];
    const float* W1 = (const float*)d_in[3];
    const float* b1 = (const float*)d_in[4];
    const float* W2 = (const float*)d_in[5];
    const float* b2 = (const float*)d_in[6];
    const float* W3 = (const float*)d_in[7];
    const float* b3 = (const float*)d_in[8];
    const float* W4 = (const float*)d_in[9];
    const float* b4 = (const float*)d_in[10];
    float* out = (float*)d_out;

    const int E = in_sizes[1] / 2;
    const int NBN = (N_NODES + 127) / 128;      // 391
    const int NTE = (E + TILE_E - 1) / TILE_E;  // 50000

    cudaFuncSetAttribute(pre_both_kernel,
                         cudaFuncAttributeMaxDynamicSharedMemorySize, PB_SMEM);
    cudaFuncSetAttribute(node_fused_kernel,
                         cudaFuncAttributeMaxDynamicSharedMemorySize, PB_SMEM);
    cudaFuncSetAttribute(edge_kernel_mma,
                         cudaFuncAttributeMaxDynamicSharedMemorySize, EDGE_SMEM_BYTES);

    zero_kernel<<<1024, 256>>>();
    prep1_kernel<<<129, 128>>>(W2, W3, b2);
    prep2_kernel<<<64, 256>>>(W1, W3, W4);
    pre_both_kernel<<<NBN, 256, PB_SMEM>>>(node_feat, b1, b3);
    edge_kernel_mma<<<296, EDGE_THREADS, EDGE_SMEM_BYTES>>>(ea, eidx, E, NTE);
    node_fused_kernel<<<NBN, 256, PB_SMEM>>>(b4, out);
}

// round 12
// speedup vs baseline: 1.0043x; 1.0043x over previous
#include <cuda_runtime.h>
#include <cuda_bf16.h>
#include <cstdint>

#define N_NODES 50000
#define HID 128
#define EF 64

// ---------------------------------------------------------------------------
// Scratch (device globals — allocation-free per harness rules)
__device__ float g_P   [(size_t)N_NODES * HID];   // node_feat@W1_top+b1
__device__ float g_P3  [(size_t)N_NODES * HID];   // node_feat@W3_top+b3
__device__ float g_sums[(size_t)N_NODES * HID];   // scatter-add of relu-h
__device__ float g_cnt [N_NODES];
__device__ float g_W23 [128 * 128];               // W2 @ W3_bot (fp32)
__device__ float g_b23 [128];                     // b2 @ W3_bot
// bf16 hi/lo weight images, [N][K] K-major 128B rows, SW128-swizzled.
// [0,16K) B1hi | [16K,32K) B1lo | then 4 node weights x 64KB each.
// widx: 0=W1_top 1=W3_top 2=W23 3=W4
__device__ __align__(16) unsigned char g_WB[32768 + 4 * 65536];

__device__ __forceinline__ uint32_t smem_u32(const void* p) {
    uint32_t a;
    asm("{ .reg .u64 t; cvta.to.shared.u64 t, %1; cvt.u32.u64 %0, t; }"
        : "=r"(a) : "l"(p));
    return a;
}
__device__ __forceinline__ uint32_t swz(uint32_t b) { return b ^ ((b >> 3) & 0x70); }

__device__ __forceinline__ void ldsm_x4(uint32_t* r, uint32_t addr) {
    asm volatile("ldmatrix.sync.aligned.m8n8.x4.shared.b16 {%0,%1,%2,%3}, [%4];"
                 : "=r"(r[0]), "=r"(r[1]), "=r"(r[2]), "=r"(r[3]) : "r"(addr));
}
__device__ __forceinline__ void mma_bf16(float* d, const uint32_t* a, const uint32_t* b) {
    asm volatile("mma.sync.aligned.m16n8k16.row.col.f32.bf16.bf16.f32 "
                 "{%0,%1,%2,%3}, {%4,%5,%6,%7}, {%8,%9}, {%0,%1,%2,%3};"
                 : "+f"(d[0]), "+f"(d[1]), "+f"(d[2]), "+f"(d[3])
                 : "r"(a[0]), "r"(a[1]), "r"(a[2]), "r"(a[3]), "r"(b[0]), "r"(b[1]));
}
__device__ __forceinline__ uint32_t pack_bf16x2(float x, float y) {
    __nv_bfloat162 p = {__float2bfloat16(x), __float2bfloat16(y)};
    return *(uint32_t*)&p;
}
__device__ __forceinline__ void split2(float x, float y, uint32_t& hi, uint32_t& lo) {
    __nv_bfloat16 hx = __float2bfloat16(x), hy = __float2bfloat16(y);
    __nv_bfloat162 ph = {hx, hy};
    hi = *(uint32_t*)&ph;
    lo = pack_bf16x2(x - __bfloat162float(hx), y - __bfloat162float(hy));
}
__device__ __forceinline__ void split8(float4 v0, float4 v1, uint4& hi, uint4& lo) {
    split2(v0.x, v0.y, hi.x, lo.x);
    split2(v0.z, v0.w, hi.y, lo.y);
    split2(v1.x, v1.y, hi.z, lo.z);
    split2(v1.z, v1.w, hi.w, lo.w);
}

// Shared K=128 bf16x3 GEMM core with x4 B-operand ldmatrix (256-thr kernels).
__device__ __forceinline__ void gemm128_core(
    uint32_t smb, uint32_t aoff, uint32_t woff, int lid,
    int arow, int akof, float acc[16][4]) {
    const int ntoff = lid >> 4;
    const int brow = lid & 7;
    const int bkof = ((lid >> 3) & 1) << 4;
    #pragma unroll
    for (int kt = 0; kt < 8; kt++) {
        const int chunk = (kt >> 2) * 16384;
        const int kb = (kt & 3) * 32;
        uint32_t ahi[4], alo[4];
        ldsm_x4(ahi, smb + aoff + chunk + swz(arow * 128 + kb + akof));
        ldsm_x4(alo, smb + aoff + 32768 + chunk + swz(arow * 128 + kb + akof));
        #pragma unroll
        for (int nt = 0; nt < 16; nt += 2) {
            uint32_t bo = swz(((nt + ntoff) * 8 + brow) * 128 + kb + bkof);
            uint32_t bh[4], bl[4];
            ldsm_x4(bh, smb + woff + chunk + bo);
            ldsm_x4(bl, smb + woff + 32768 + chunk + bo);
            mma_bf16(acc[nt],     ahi, bh);
            mma_bf16(acc[nt],     ahi, bl);
            mma_bf16(acc[nt],     alo, bh);
            mma_bf16(acc[nt + 1], ahi, bh + 2);
            mma_bf16(acc[nt + 1], ahi, bl + 2);
            mma_bf16(acc[nt + 1], alo, bh + 2);
        }
    }
}

// ---------------------------------------------------------------------------
__global__ void zero_kernel() {
    const size_t total4 = (size_t)N_NODES * HID / 4;
    float4* s = (float4*)g_sums;
    const float4 z = make_float4(0.f, 0.f, 0.f, 0.f);
    for (size_t i = (size_t)blockIdx.x * blockDim.x + threadIdx.x; i < total4;
         i += (size_t)gridDim.x * blockDim.x)
        s[i] = z;
    for (int i = blockIdx.x * blockDim.x + threadIdx.x; i < N_NODES;
         i += gridDim.x * blockDim.x)
        g_cnt[i] = 0.f;
}

// ---------------------------------------------------------------------------
// W23 = W2 @ W3[128:256], b23 = b2 @ W3[128:256]
__global__ void prep1_kernel(const float* __restrict__ W2,
                             const float* __restrict__ W3,
                             const float* __restrict__ b2) {
    __shared__ float srow[128];
    const int r = blockIdx.x;
    const int c = threadIdx.x;
    srow[c] = (r < 128) ? W2[r * 128 + c] : b2[c];
    __syncthreads();
    float acc = 0.f;
    #pragma unroll 4
    for (int k = 0; k < 128; k++)
        acc += srow[k] * W3[(128 + k) * 128 + c];
    if (r < 128) g_W23[r * 128 + c] = acc;
    else         g_b23[c] = acc;
}

// ---------------------------------------------------------------------------
__global__ void prep2_kernel(const float* __restrict__ W1,
                             const float* __restrict__ W3,
                             const float* __restrict__ W4) {
    const int tid = blockIdx.x * blockDim.x + threadIdx.x;
    const int nth = gridDim.x * blockDim.x;
    for (int i = tid; i < 128 * 64; i += nth) {       // edge B1 = W1 rows 128..191
        int n = i >> 6, k = i & 63;
        float v = W1[(128 + k) * 128 + n];
        __nv_bfloat16 h = __float2bfloat16(v);
        __nv_bfloat16 l = __float2bfloat16(v - __bfloat162float(h));
        uint32_t off = swz(n * 128 + k * 2);
        *(__nv_bfloat16*)(g_WB + off)         = h;
        *(__nv_bfloat16*)(g_WB + 16384 + off) = l;
    }
    for (int i = tid; i < 4 * 128 * 128; i += nth) {  // node weights
        int widx = i >> 14, j = i & 16383;
        int n = j >> 7, k = j & 127;
        float v;
        if      (widx == 0) v = W1[k * 128 + n];
        else if (widx == 1) v = W3[k * 128 + n];
        else if (widx == 2) v = g_W23[k * 128 + n];
        else                v = W4[k * 128 + n];
        __nv_bfloat16 h = __float2bfloat16(v);
        __nv_bfloat16 l = __float2bfloat16(v - __bfloat162float(h));
        int c = k >> 6, kk = k & 63;
        uint32_t off = swz(n * 128 + kk * 2);
        unsigned char* base = g_WB + 32768 + widx * 65536;
        *(__nv_bfloat16*)(base + c * 16384 + off)         = h;
        *(__nv_bfloat16*)(base + 32768 + c * 16384 + off) = l;
    }
}

// ---------------------------------------------------------------------------
// pre_both: stage node_feat once; P = nf@W1t + b1; P3 = nf@W3t + b3.
#define PB_W 0
#define PB_A 65536
#define PB_BIAS 131072
#define PB_SMEM (131072 + 1024)

__global__ __launch_bounds__(256, 1)
void pre_both_kernel(const float* __restrict__ A, const float* __restrict__ b1,
                     const float* __restrict__ b3) {
    extern __shared__ char smc[];
    const uint32_t smb = smem_u32(smc);
    const int tid = threadIdx.x;
    const int wid = tid >> 5;
    const int lid = tid & 31;
    float* s_b1 = (float*)(smc + PB_BIAS);
    float* s_b3 = s_b1 + 128;

    {
        const float4* src = (const float4*)(g_WB + 32768);
        float4* dst = (float4*)smc;
        #pragma unroll
        for (int i = 0; i < 16; i++) dst[tid + 256 * i] = src[tid + 256 * i];
    }
    if (tid < 128) { s_b1[tid] = b1[tid]; s_b3[tid] = b3[tid]; }

    const int m0 = blockIdx.x * 128;
    {
        const int r = tid >> 1;
        const int chunk = tid & 1;
        const int gr = m0 + r;
        const bool valid = gr < N_NODES;
        const float* src = A + (size_t)gr * 128 + chunk * 64;
        #pragma unroll
        for (int j = 0; j < 8; j++) {
            float4 v0 = valid ? *(const float4*)(src + j * 8)
                              : make_float4(0.f, 0.f, 0.f, 0.f);
            float4 v1 = valid ? *(const float4*)(src + j * 8 + 4)
                              : make_float4(0.f, 0.f, 0.f, 0.f);
            uint4 hi, lo;
            split8(v0, v1, hi, lo);
            uint32_t off = swz(r * 128 + j * 16);
            *(uint4*)(smc + PB_A + chunk * 16384 + off) = hi;
            *(uint4*)(smc + PB_A + 32768 + chunk * 16384 + off) = lo;
        }
    }
    __syncthreads();

    const int wr0 = wid * 16;
    const int qr = lid >> 2, qc = (lid & 3) * 2;
    const int r0 = wr0 + qr, r1 = r0 + 8;
    const int am = lid >> 3;
    const int arow = wr0 + ((am & 1) << 3) + (lid & 7);
    const int akof = (am >> 1) << 4;
    const int gr0 = m0 + r0, gr1 = m0 + r1;

    float acc[16][4];
    #pragma unroll
    for (int nt = 0; nt < 16; nt++)
        #pragma unroll
        for (int v = 0; v < 4; v++) acc[nt][v] = 0.f;
    gemm128_core(smb, PB_A, PB_W, lid, arow, akof, acc);
    #pragma unroll
    for (int nt = 0; nt < 16; nt++) {
        const int c = nt * 8 + qc;
        if (gr0 < N_NODES)
            *(float2*)(g_P + (size_t)gr0 * 128 + c) = make_float2(
                acc[nt][0] + s_b1[c], acc[nt][1] + s_b1[c + 1]);
        if (gr1 < N_NODES)
            *(float2*)(g_P + (size_t)gr1 * 128 + c) = make_float2(
                acc[nt][2] + s_b1[c], acc[nt][3] + s_b1[c + 1]);
    }
    __syncthreads();
    {
        const float4* src = (const float4*)(g_WB + 32768 + 65536);
        float4* dst = (float4*)smc;
        #pragma unroll
        for (int i = 0; i < 16; i++) dst[tid + 256 * i] = src[tid + 256 * i];
    }
    __syncthreads();
    #pragma unroll
    for (int nt = 0; nt < 16; nt++)
        #pragma unroll
        for (int v = 0; v < 4; v++) acc[nt][v] = 0.f;
    gemm128_core(smb, PB_A, PB_W, lid, arow, akof, acc);
    #pragma unroll
    for (int nt = 0; nt < 16; nt++) {
        const int c = nt * 8 + qc;
        if (gr0 < N_NODES)
            *(float2*)(g_P3 + (size_t)gr0 * 128 + c) = make_float2(
                acc[nt][0] + s_b3[c], acc[nt][1] + s_b3[c + 1]);
        if (gr1 < N_NODES)
            *(float2*)(g_P3 + (size_t)gr1 * 128 + c) = make_float2(
                acc[nt][2] + s_b3[c], acc[nt][3] + s_b3[c + 1]);
    }
}

// ---------------------------------------------------------------------------
// node_fused: mean = sums/max(cnt,1); T = relu(P3 + mean@W23 + flag*b23);
// out = T@W4 + b4.
__global__ __launch_bounds__(256, 1)
void node_fused_kernel(const float* __restrict__ b4, float* __restrict__ out) {
    extern __shared__ char smc[];
    const uint32_t smb = smem_u32(smc);
    const int tid = threadIdx.x;
    const int wid = tid >> 5;
    const int lid = tid & 31;
    float* s_b23 = (float*)(smc + PB_BIAS);
    float* s_b4  = s_b23 + 128;

    {
        const float4* src = (const float4*)(g_WB + 32768 + 2 * 65536);
        float4* dst = (float4*)smc;
        #pragma unroll
        for (int i = 0; i < 16; i++) dst[tid + 256 * i] = src[tid + 256 * i];
    }
    if (tid < 128) { s_b23[tid] = g_b23[tid]; s_b4[tid] = b4[tid]; }

    const int m0 = blockIdx.x * 128;
    {
        const int r = tid >> 1;
        const int chunk = tid & 1;
        const int gr = m0 + r;
        const bool valid = gr < N_NODES;
        float s = valid ? 1.f / fmaxf(g_cnt[gr], 1.f) : 0.f;
        const float* src = g_sums + (size_t)gr * 128 + chunk * 64;
        #pragma unroll
        for (int j = 0; j < 8; j++) {
            float4 v0 = valid ? *(const float4*)(src + j * 8)
                              : make_float4(0.f, 0.f, 0.f, 0.f);
            float4 v1 = valid ? *(const float4*)(src + j * 8 + 4)
                              : make_float4(0.f, 0.f, 0.f, 0.f);
            v0.x *= s; v0.y *= s; v0.z *= s; v0.w *= s;
            v1.x *= s; v1.y *= s; v1.z *= s; v1.w *= s;
            uint4 hi, lo;
            split8(v0, v1, hi, lo);
            uint32_t off = swz(r * 128 + j * 16);
            *(uint4*)(smc + PB_A + chunk * 16384 + off) = hi;
            *(uint4*)(smc + PB_A + 32768 + chunk * 16384 + off) = lo;
        }
    }
    __syncthreads();

    const int wr0 = wid * 16;
    const int qr = lid >> 2, qc = (lid & 3) * 2;
    const int r0 = wr0 + qr, r1 = r0 + 8;
    const int am = lid >> 3;
    const int arow = wr0 + ((am & 1) << 3) + (lid & 7);
    const int akof = (am >> 1) << 4;
    const int gr0 = m0 + r0, gr1 = m0 + r1;

    float acc[16][4];
    #pragma unroll
    for (int nt = 0; nt < 16; nt++)
        #pragma unroll
        for (int v = 0; v < 4; v++) acc[nt][v] = 0.f;
    gemm128_core(smb, PB_A, PB_W, lid, arow, akof, acc);

    {
        const float f0 = (gr0 < N_NODES && g_cnt[gr0] > 0.f) ? 1.f : 0.f;
        const float f1 = (gr1 < N_NODES && g_cnt[gr1] > 0.f) ? 1.f : 0.f;
        #pragma unroll
        for (int nt = 0; nt < 16; nt++) {
            const int c = nt * 8 + qc;
            float t00 = 0.f, t01 = 0.f, t10 = 0.f, t11 = 0.f;
            if (gr0 < N_NODES) {
                float2 p = *(const float2*)(g_P3 + (size_t)gr0 * 128 + c);
                t00 = fmaxf(p.x + acc[nt][0] + f0 * s_b23[c], 0.f);
                t01 = fmaxf(p.y + acc[nt][1] + f0 * s_b23[c + 1], 0.f);
            }
            if (gr1 < N_NODES) {
                float2 p = *(const float2*)(g_P3 + (size_t)gr1 * 128 + c);
                t10 = fmaxf(p.x + acc[nt][2] + f1 * s_b23[c], 0.f);
                t11 = fmaxf(p.y + acc[nt][3] + f1 * s_b23[c + 1], 0.f);
            }
            uint32_t hi0, lo0, hi1, lo1;
            split2(t00, t01, hi0, lo0);
            split2(t10, t11, hi1, lo1);
            const int chunk = (c >> 6) * 16384;
            const int kk2 = (c & 63) * 2;
            *(uint32_t*)(smc + PB_A + chunk + swz(r0 * 128 + kk2)) = hi0;
            *(uint32_t*)(smc + PB_A + chunk + swz(r1 * 128 + kk2)) = hi1;
            *(uint32_t*)(smc + PB_A + 32768 + chunk + swz(r0 * 128 + kk2)) = lo0;
            *(uint32_t*)(smc + PB_A + 32768 + chunk + swz(r1 * 128 + kk2)) = lo1;
        }
    }
    __syncthreads();
    {
        const float4* src = (const float4*)(g_WB + 32768 + 3 * 65536);
        float4* dst = (float4*)smc;
        #pragma unroll
        for (int i = 0; i < 16; i++) dst[tid + 256 * i] = src[tid + 256 * i];
    }
    __syncthreads();
    #pragma unroll
    for (int nt = 0; nt < 16; nt++)
        #pragma unroll
        for (int v = 0; v < 4; v++) acc[nt][v] = 0.f;
    gemm128_core(smb, PB_A, PB_W, lid, arow, akof, acc);
    #pragma unroll
    for (int nt = 0; nt < 16; nt++) {
        const int c = nt * 8 + qc;
        if (gr0 < N_NODES)
            *(float2*)(out + (size_t)gr0 * 128 + c) = make_float2(
                acc[nt][0] + s_b4[c], acc[nt][1] + s_b4[c + 1]);
        if (gr1 < N_NODES)
            *(float2*)(out + (size_t)gr1 * 128 + c) = make_float2(
                acc[nt][2] + s_b4[c], acc[nt][3] + s_b4[c + 1]);
    }
}

// ---------------------------------------------------------------------------
// Edge kernel: 256 threads, 2 CTAs/SM, 64-edge tiles (R10 geometry), with
// B1hi fragments HOISTED INTO REGISTERS (64 regs/thread, loaded by ldmatrix
// once). B1lo stays in SMEM. Per-tile B-LDSM traffic halves with no change
// to tile-loop overheads. Double-buffered A staging, prefetch of P rows,
// one __syncthreads per tile.
// SMEM: [0,16K) B1hi | 16K B1lo | 32K A0hi | 40K A0lo | 48K A1hi | 56K A1lo
//       | 64K idx (2 x 128 ints)
#define SM_B1HI 0
#define SM_B1LO 16384
#define SM_A    32768
#define SM_IDX  65536
#define EDGE_SMEM_BYTES (65536 + 1280)
#define EDGE_THREADS 256
#define TILE_E 64

__global__ __launch_bounds__(EDGE_THREADS, 2)
void edge_kernel_mma(const float* __restrict__ ea, const int* __restrict__ eidx,
                     int E, int ntiles) {
    extern __shared__ char smc[];
    const uint32_t smb = smem_u32(smc);
    const int tid = threadIdx.x;
    const int wid = tid >> 5;
    const int lid = tid & 31;

    {   // weights once (32 KB)
        const float4* src = (const float4*)g_WB;
        float4* dst = (float4*)smc;
        for (int i = tid; i < 2048; i += EDGE_THREADS) dst[i] = src[i];
    }
    __syncthreads();

    // MMA lane geometry: 4 row strips x 2 col halves
    const int rstrip = (wid >> 1) * 16;
    const int chalf  = (wid & 1) * 64;
    const int qr = lid >> 2;
    const int r0 = rstrip + qr, r1 = r0 + 8;
    const int am = lid >> 3;
    const int arow = rstrip + ((am & 1) << 3) + (lid & 7);
    const int akof = (am >> 1) << 4;
    const int ntoff = lid >> 4;
    const int brow = lid & 7;
    const int bkof = ((lid >> 3) & 1) << 4;

    // ---- hoist B1hi fragments into registers (loaded once) ----
    // Bh[kt][pair][4]: pair p covers nt = p*2 + ntoff within the warp's
    // 64-col half (8 nt blocks -> 4 x4-pairs).
    uint32_t Bh[4][4][4];
    #pragma unroll
    for (int kt = 0; kt < 4; kt++) {
        const int kb = kt * 32;
        #pragma unroll
        for (int pr = 0; pr < 4; pr++) {
            const int ntg = (chalf >> 3) + pr * 2 + ntoff;
            uint32_t bo = swz((ntg * 8 + brow) * 128 + kb + bkof);
            ldsm_x4(Bh[kt][pr], smb + SM_B1HI + bo);
        }
    }

    // staging lane geometry (4 threads/row, 16 floats each; 64 rows)
    const int st_r = tid >> 2;
    const int st_q = tid & 3;

    // epilogue shuffle geometry
    const int cboff = (lid & 2) ? 4 : 0;
    const bool evenlane = ((lid & 1) == 0);
    const int myrow = evenlane ? r0 : r1;

    // ---- stage helper: 64-edge tile into buffer q ----
    auto stage = [&](int tile, int q) {
        const int e0s = tile * TILE_E;
        int* rowq = (int*)(smc + SM_IDX) + q * 128;
        int* colq = rowq + 64;
        if (tid < 64) {
            int e = e0s + tid;
            rowq[tid] = (e < E) ? eidx[e] : 0;
        } else if (tid < 128) {
            int t = tid - 64, e = e0s + t;
            colq[t] = (e < E) ? eidx[(size_t)E + e] : 0;
        }
        const int e = e0s + st_r;
        const bool valid = e < E;
        const float* src = ea + (size_t)e * EF + st_q * 16;
        const uint32_t abase = (uint32_t)(SM_A + q * 16384);
        #pragma unroll
        for (int j = 0; j < 2; j++) {
            float4 v0 = valid ? *(const float4*)(src + j * 8)
                              : make_float4(0.f, 0.f, 0.f, 0.f);
            float4 v1 = valid ? *(const float4*)(src + j * 8 + 4)
                              : make_float4(0.f, 0.f, 0.f, 0.f);
            uint4 hi, lo;
            split8(v0, v1, hi, lo);
            uint32_t off = swz(st_r * 128 + st_q * 32 + j * 16);
            *(uint4*)(smc + abase + off) = hi;
            *(uint4*)(smc + abase + 8192 + off) = lo;
        }
    };

    if (blockIdx.x < ntiles) stage(blockIdx.x, 0);
    __syncthreads();

    int p = 0;
    for (int tile = blockIdx.x; tile < ntiles; tile += gridDim.x, p ^= 1) {
        const int e0 = tile * TILE_E;
        const int* rowp = (const int*)(smc + SM_IDX) + p * 128;
        const int* colp = rowp + 64;
        const uint32_t aoff = (uint32_t)(SM_A + p * 16384);

        // ---- prefetch this thread's P-row segment to L1 (overlaps GEMM) ----
        const int srcnode = colp[myrow];
        const float* Pbase = g_P + (size_t)srcnode * 128 + chalf;
        asm volatile("prefetch.global.L1 [%0];" :: "l"(Pbase));
        asm volatile("prefetch.global.L1 [%0];" :: "l"(Pbase + 32));

        // ---- GEMM1: 8 nt per warp; Bhi from regs, Blo from SMEM ----
        float acc[8][4];
        #pragma unroll
        for (int nt = 0; nt < 8; nt++)
            #pragma unroll
            for (int v = 0; v < 4; v++) acc[nt][v] = 0.f;
        #pragma unroll
        for (int kt = 0; kt < 4; kt++) {
            const int kb = kt * 32;
            uint32_t ahi[4], alo[4];
            ldsm_x4(ahi, smb + aoff + swz(arow * 128 + kb + akof));
            ldsm_x4(alo, smb + aoff + 8192 + swz(arow * 128 + kb + akof));
            #pragma unroll
            for (int pr = 0; pr < 4; pr++) {
                const int nt = pr * 2;
                const int ntg = (chalf >> 3) + nt + ntoff;
                uint32_t bo = swz((ntg * 8 + brow) * 128 + kb + bkof);
                uint32_t bl[4];
                ldsm_x4(bl, smb + SM_B1LO + bo);
                mma_bf16(acc[nt],     ahi, Bh[kt][pr]);
                mma_bf16(acc[nt],     ahi, bl);
                mma_bf16(acc[nt],     alo, Bh[kt][pr]);
                mma_bf16(acc[nt + 1], ahi, Bh[kt][pr] + 2);
                mma_bf16(acc[nt + 1], ahi, bl + 2);
                mma_bf16(acc[nt + 1], alo, Bh[kt][pr] + 2);
            }
        }

        // ---- stage NEXT tile into the other buffer (overlaps epilogue) ----
        const int nxt = tile + gridDim.x;
        if (nxt < ntiles) stage(nxt, 1 - p);

        // ---- epilogue: shuffle to float4; h = relu(D1 + P[col]); RED.F32X4
        {
            const bool valid = (e0 + myrow < E);
            const float* Pn = Pbase + cboff;
            float* Sn = g_sums + (size_t)rowp[myrow] * 128 + chalf + cboff;
            #pragma unroll
            for (int nt = 0; nt < 8; nt++) {
                float sA = evenlane ? acc[nt][2] : acc[nt][0];
                float sB = evenlane ? acc[nt][3] : acc[nt][1];
                float rA = __shfl_xor_sync(0xFFFFFFFFu, sA, 1);
                float rB = __shfl_xor_sync(0xFFFFFFFFu, sB, 1);
                float4 v = evenlane
                    ? make_float4(acc[nt][0], acc[nt][1], rA, rB)
                    : make_float4(rA, rB, acc[nt][2], acc[nt][3]);
                if (valid) {
                    float4 pv = *(const float4*)(Pn + nt * 8);
                    v.x = fmaxf(v.x + pv.x, 0.f);
                    v.y = fmaxf(v.y + pv.y, 0.f);
                    v.z = fmaxf(v.z + pv.z, 0.f);
                    v.w = fmaxf(v.w + pv.w, 0.f);
                    atomicAdd((float4*)(Sn + nt * 8), v);
                }
            }
        }
        if (tid < 64 && e0 + tid < E) atomicAdd(&g_cnt[rowp[tid]], 1.0f);

        __syncthreads();   // buffer 1-p fully staged; buffer p free to rewrite
    }
}

// ---------------------------------------------------------------------------
extern "C" void kernel_launch(void* const* d_in, const int* in_sizes, int n_in,
                              void* d_out, int out_size) {
    const float* node_feat = (const float*)d_in[0];
    const int*   eidx      = (const int*)d_in[1];   // int32 (JAX x64 disabled)
    const float* ea        = (const float*)d_in[2];
    const float* W1 = (const float*)d_in[3];
    const float* b1 = (const float*)d_in[4];
    const float* W2 = (const float*)d_in[5];
    const float* b2 = (const float*)d_in[6];
    const float* W3 = (const float*)d_in[7];
    const float* b3 = (const float*)d_in[8];
    const float* W4 = (const float*)d_in[9];
    const float* b4 = (const float*)d_in[10];
    float* out = (float*)d_out;

    const int E = in_sizes[1] / 2;
    const int NBN = (N_NODES + 127) / 128;      // 391
    const int NTE = (E + TILE_E - 1) / TILE_E;  // 25000

    cudaFuncSetAttribute(pre_both_kernel,
                         cudaFuncAttributeMaxDynamicSharedMemorySize, PB_SMEM);
    cudaFuncSetAttribute(node_fused_kernel,
                         cudaFuncAttributeMaxDynamicSharedMemorySize, PB_SMEM);
    cudaFuncSetAttribute(edge_kernel_mma,
                         cudaFuncAttributeMaxDynamicSharedMemorySize, EDGE_SMEM_BYTES);

    zero_kernel<<<1024, 256>>>();
    prep1_kernel<<<129, 128>>>(W2, W3, b2);
    prep2_kernel<<<64, 256>>>(W1, W3, W4);
    pre_both_kernel<<<NBN, 256, PB_SMEM>>>(node_feat, b1, b3);
    edge_kernel_mma<<<296, EDGE_THREADS, EDGE_SMEM_BYTES>>>(ea, eidx, E, NTE);
    node_fused_kernel<<<NBN, 256, PB_SMEM>>>(b4, out);
}

// round 13
// speedup vs baseline: 1.0443x; 1.0399x over previous
#include <cuda_runtime.h>
#include <cuda_bf16.h>
#include <cstdint>

#define N_NODES 50000
#define HID 128
#define EF 64

// ---------------------------------------------------------------------------
// Scratch (device globals — allocation-free per harness rules)
__device__ float g_P   [(size_t)N_NODES * HID];   // node_feat@W1_top+b1
__device__ float g_P3  [(size_t)N_NODES * HID];   // node_feat@W3_top+b3
__device__ float g_sums[(size_t)N_NODES * HID];   // scatter-add of relu-h
__device__ float g_cnt [N_NODES];
__device__ float g_W23 [128 * 128];               // W2 @ W3_bot (fp32)
__device__ float g_b23 [128];                     // b2 @ W3_bot
// bf16 hi/lo weight images, [N][K] K-major 128B rows, SW128-swizzled.
// [0,16K) B1hi | [16K,32K) B1lo | then 4 node weights x 64KB each.
// widx: 0=W1_top 1=W3_top 2=W23 3=W4
__device__ __align__(16) unsigned char g_WB[32768 + 4 * 65536];

__device__ __forceinline__ uint32_t smem_u32(const void* p) {
    uint32_t a;
    asm("{ .reg .u64 t; cvta.to.shared.u64 t, %1; cvt.u32.u64 %0, t; }"
        : "=r"(a) : "l"(p));
    return a;
}
__device__ __forceinline__ uint32_t swz(uint32_t b) { return b ^ ((b >> 3) & 0x70); }

__device__ __forceinline__ void ldsm_x4(uint32_t* r, uint32_t addr) {
    asm volatile("ldmatrix.sync.aligned.m8n8.x4.shared.b16 {%0,%1,%2,%3}, [%4];"
                 : "=r"(r[0]), "=r"(r[1]), "=r"(r[2]), "=r"(r[3]) : "r"(addr));
}
__device__ __forceinline__ void mma_bf16(float* d, const uint32_t* a, const uint32_t* b) {
    asm volatile("mma.sync.aligned.m16n8k16.row.col.f32.bf16.bf16.f32 "
                 "{%0,%1,%2,%3}, {%4,%5,%6,%7}, {%8,%9}, {%0,%1,%2,%3};"
                 : "+f"(d[0]), "+f"(d[1]), "+f"(d[2]), "+f"(d[3])
                 : "r"(a[0]), "r"(a[1]), "r"(a[2]), "r"(a[3]), "r"(b[0]), "r"(b[1]));
}
__device__ __forceinline__ uint32_t pack_bf16x2(float x, float y) {
    __nv_bfloat162 p = {__float2bfloat16(x), __float2bfloat16(y)};
    return *(uint32_t*)&p;
}
__device__ __forceinline__ void split2(float x, float y, uint32_t& hi, uint32_t& lo) {
    __nv_bfloat16 hx = __float2bfloat16(x), hy = __float2bfloat16(y);
    __nv_bfloat162 ph = {hx, hy};
    hi = *(uint32_t*)&ph;
    lo = pack_bf16x2(x - __bfloat162float(hx), y - __bfloat162float(hy));
}
__device__ __forceinline__ void split8(float4 v0, float4 v1, uint4& hi, uint4& lo) {
    split2(v0.x, v0.y, hi.x, lo.x);
    split2(v0.z, v0.w, hi.y, lo.y);
    split2(v1.x, v1.y, hi.z, lo.z);
    split2(v1.z, v1.w, hi.w, lo.w);
}

// Shared K=128 bf16x3 GEMM core with x4 B-operand ldmatrix (256-thr kernels).
__device__ __forceinline__ void gemm128_core(
    uint32_t smb, uint32_t aoff, uint32_t woff, int lid,
    int arow, int akof, float acc[16][4]) {
    const int ntoff = lid >> 4;
    const int brow = lid & 7;
    const int bkof = ((lid >> 3) & 1) << 4;
    #pragma unroll
    for (int kt = 0; kt < 8; kt++) {
        const int chunk = (kt >> 2) * 16384;
        const int kb = (kt & 3) * 32;
        uint32_t ahi[4], alo[4];
        ldsm_x4(ahi, smb + aoff + chunk + swz(arow * 128 + kb + akof));
        ldsm_x4(alo, smb + aoff + 32768 + chunk + swz(arow * 128 + kb + akof));
        #pragma unroll
        for (int nt = 0; nt < 16; nt += 2) {
            uint32_t bo = swz(((nt + ntoff) * 8 + brow) * 128 + kb + bkof);
            uint32_t bh[4], bl[4];
            ldsm_x4(bh, smb + woff + chunk + bo);
            ldsm_x4(bl, smb + woff + 32768 + chunk + bo);
            mma_bf16(acc[nt],     ahi, bh);
            mma_bf16(acc[nt],     ahi, bl);
            mma_bf16(acc[nt],     alo, bh);
            mma_bf16(acc[nt + 1], ahi, bh + 2);
            mma_bf16(acc[nt + 1], ahi, bl + 2);
            mma_bf16(acc[nt + 1], alo, bh + 2);
        }
    }
}

// ---------------------------------------------------------------------------
__global__ void zero_kernel() {
    const size_t total4 = (size_t)N_NODES * HID / 4;
    float4* s = (float4*)g_sums;
    const float4 z = make_float4(0.f, 0.f, 0.f, 0.f);
    for (size_t i = (size_t)blockIdx.x * blockDim.x + threadIdx.x; i < total4;
         i += (size_t)gridDim.x * blockDim.x)
        s[i] = z;
    for (int i = blockIdx.x * blockDim.x + threadIdx.x; i < N_NODES;
         i += gridDim.x * blockDim.x)
        g_cnt[i] = 0.f;
}

// ---------------------------------------------------------------------------
// W23 = W2 @ W3[128:256], b23 = b2 @ W3[128:256]
__global__ void prep1_kernel(const float* __restrict__ W2,
                             const float* __restrict__ W3,
                             const float* __restrict__ b2) {
    __shared__ float srow[128];
    const int r = blockIdx.x;
    const int c = threadIdx.x;
    srow[c] = (r < 128) ? W2[r * 128 + c] : b2[c];
    __syncthreads();
    float acc = 0.f;
    #pragma unroll 4
    for (int k = 0; k < 128; k++)
        acc += srow[k] * W3[(128 + k) * 128 + c];
    if (r < 128) g_W23[r * 128 + c] = acc;
    else         g_b23[c] = acc;
}

// ---------------------------------------------------------------------------
__global__ void prep2_kernel(const float* __restrict__ W1,
                             const float* __restrict__ W3,
                             const float* __restrict__ W4) {
    const int tid = blockIdx.x * blockDim.x + threadIdx.x;
    const int nth = gridDim.x * blockDim.x;
    for (int i = tid; i < 128 * 64; i += nth) {       // edge B1 = W1 rows 128..191
        int n = i >> 6, k = i & 63;
        float v = W1[(128 + k) * 128 + n];
        __nv_bfloat16 h = __float2bfloat16(v);
        __nv_bfloat16 l = __float2bfloat16(v - __bfloat162float(h));
        uint32_t off = swz(n * 128 + k * 2);
        *(__nv_bfloat16*)(g_WB + off)         = h;
        *(__nv_bfloat16*)(g_WB + 16384 + off) = l;
    }
    for (int i = tid; i < 4 * 128 * 128; i += nth) {  // node weights
        int widx = i >> 14, j = i & 16383;
        int n = j >> 7, k = j & 127;
        float v;
        if      (widx == 0) v = W1[k * 128 + n];
        else if (widx == 1) v = W3[k * 128 + n];
        else if (widx == 2) v = g_W23[k * 128 + n];
        else                v = W4[k * 128 + n];
        __nv_bfloat16 h = __float2bfloat16(v);
        __nv_bfloat16 l = __float2bfloat16(v - __bfloat162float(h));
        int c = k >> 6, kk = k & 63;
        uint32_t off = swz(n * 128 + kk * 2);
        unsigned char* base = g_WB + 32768 + widx * 65536;
        *(__nv_bfloat16*)(base + c * 16384 + off)         = h;
        *(__nv_bfloat16*)(base + 32768 + c * 16384 + off) = l;
    }
}

// ---------------------------------------------------------------------------
// pre_both: stage node_feat once; P = nf@W1t + b1; P3 = nf@W3t + b3.
#define PB_W 0
#define PB_A 65536
#define PB_BIAS 131072
#define PB_SMEM (131072 + 1024)

__global__ __launch_bounds__(256, 1)
void pre_both_kernel(const float* __restrict__ A, const float* __restrict__ b1,
                     const float* __restrict__ b3) {
    extern __shared__ char smc[];
    const uint32_t smb = smem_u32(smc);
    const int tid = threadIdx.x;
    const int wid = tid >> 5;
    const int lid = tid & 31;
    float* s_b1 = (float*)(smc + PB_BIAS);
    float* s_b3 = s_b1 + 128;

    {
        const float4* src = (const float4*)(g_WB + 32768);
        float4* dst = (float4*)smc;
        #pragma unroll
        for (int i = 0; i < 16; i++) dst[tid + 256 * i] = src[tid + 256 * i];
    }
    if (tid < 128) { s_b1[tid] = b1[tid]; s_b3[tid] = b3[tid]; }

    const int m0 = blockIdx.x * 128;
    {
        const int r = tid >> 1;
        const int chunk = tid & 1;
        const int gr = m0 + r;
        const bool valid = gr < N_NODES;
        const float* src = A + (size_t)gr * 128 + chunk * 64;
        #pragma unroll
        for (int j = 0; j < 8; j++) {
            float4 v0 = valid ? *(const float4*)(src + j * 8)
                              : make_float4(0.f, 0.f, 0.f, 0.f);
            float4 v1 = valid ? *(const float4*)(src + j * 8 + 4)
                              : make_float4(0.f, 0.f, 0.f, 0.f);
            uint4 hi, lo;
            split8(v0, v1, hi, lo);
            uint32_t off = swz(r * 128 + j * 16);
            *(uint4*)(smc + PB_A + chunk * 16384 + off) = hi;
            *(uint4*)(smc + PB_A + 32768 + chunk * 16384 + off) = lo;
        }
    }
    __syncthreads();

    const int wr0 = wid * 16;
    const int qr = lid >> 2, qc = (lid & 3) * 2;
    const int r0 = wr0 + qr, r1 = r0 + 8;
    const int am = lid >> 3;
    const int arow = wr0 + ((am & 1) << 3) + (lid & 7);
    const int akof = (am >> 1) << 4;
    const int gr0 = m0 + r0, gr1 = m0 + r1;

    float acc[16][4];
    #pragma unroll
    for (int nt = 0; nt < 16; nt++)
        #pragma unroll
        for (int v = 0; v < 4; v++) acc[nt][v] = 0.f;
    gemm128_core(smb, PB_A, PB_W, lid, arow, akof, acc);
    #pragma unroll
    for (int nt = 0; nt < 16; nt++) {
        const int c = nt * 8 + qc;
        if (gr0 < N_NODES)
            *(float2*)(g_P + (size_t)gr0 * 128 + c) = make_float2(
                acc[nt][0] + s_b1[c], acc[nt][1] + s_b1[c + 1]);
        if (gr1 < N_NODES)
            *(float2*)(g_P + (size_t)gr1 * 128 + c) = make_float2(
                acc[nt][2] + s_b1[c], acc[nt][3] + s_b1[c + 1]);
    }
    __syncthreads();
    {
        const float4* src = (const float4*)(g_WB + 32768 + 65536);
        float4* dst = (float4*)smc;
        #pragma unroll
        for (int i = 0; i < 16; i++) dst[tid + 256 * i] = src[tid + 256 * i];
    }
    __syncthreads();
    #pragma unroll
    for (int nt = 0; nt < 16; nt++)
        #pragma unroll
        for (int v = 0; v < 4; v++) acc[nt][v] = 0.f;
    gemm128_core(smb, PB_A, PB_W, lid, arow, akof, acc);
    #pragma unroll
    for (int nt = 0; nt < 16; nt++) {
        const int c = nt * 8 + qc;
        if (gr0 < N_NODES)
            *(float2*)(g_P3 + (size_t)gr0 * 128 + c) = make_float2(
                acc[nt][0] + s_b3[c], acc[nt][1] + s_b3[c + 1]);
        if (gr1 < N_NODES)
            *(float2*)(g_P3 + (size_t)gr1 * 128 + c) = make_float2(
                acc[nt][2] + s_b3[c], acc[nt][3] + s_b3[c + 1]);
    }
}

// ---------------------------------------------------------------------------
// node_fused: mean = sums/max(cnt,1); T = relu(P3 + mean@W23 + flag*b23);
// out = T@W4 + b4.
__global__ __launch_bounds__(256, 1)
void node_fused_kernel(const float* __restrict__ b4, float* __restrict__ out) {
    extern __shared__ char smc[];
    const uint32_t smb = smem_u32(smc);
    const int tid = threadIdx.x;
    const int wid = tid >> 5;
    const int lid = tid & 31;
    float* s_b23 = (float*)(smc + PB_BIAS);
    float* s_b4  = s_b23 + 128;

    {
        const float4* src = (const float4*)(g_WB + 32768 + 2 * 65536);
        float4* dst = (float4*)smc;
        #pragma unroll
        for (int i = 0; i < 16; i++) dst[tid + 256 * i] = src[tid + 256 * i];
    }
    if (tid < 128) { s_b23[tid] = g_b23[tid]; s_b4[tid] = b4[tid]; }

    const int m0 = blockIdx.x * 128;
    {
        const int r = tid >> 1;
        const int chunk = tid & 1;
        const int gr = m0 + r;
        const bool valid = gr < N_NODES;
        float s = valid ? 1.f / fmaxf(g_cnt[gr], 1.f) : 0.f;
        const float* src = g_sums + (size_t)gr * 128 + chunk * 64;
        #pragma unroll
        for (int j = 0; j < 8; j++) {
            float4 v0 = valid ? *(const float4*)(src + j * 8)
                              : make_float4(0.f, 0.f, 0.f, 0.f);
            float4 v1 = valid ? *(const float4*)(src + j * 8 + 4)
                              : make_float4(0.f, 0.f, 0.f, 0.f);
            v0.x *= s; v0.y *= s; v0.z *= s; v0.w *= s;
            v1.x *= s; v1.y *= s; v1.z *= s; v1.w *= s;
            uint4 hi, lo;
            split8(v0, v1, hi, lo);
            uint32_t off = swz(r * 128 + j * 16);
            *(uint4*)(smc + PB_A + chunk * 16384 + off) = hi;
            *(uint4*)(smc + PB_A + 32768 + chunk * 16384 + off) = lo;
        }
    }
    __syncthreads();

    const int wr0 = wid * 16;
    const int qr = lid >> 2, qc = (lid & 3) * 2;
    const int r0 = wr0 + qr, r1 = r0 + 8;
    const int am = lid >> 3;
    const int arow = wr0 + ((am & 1) << 3) + (lid & 7);
    const int akof = (am >> 1) << 4;
    const int gr0 = m0 + r0, gr1 = m0 + r1;

    float acc[16][4];
    #pragma unroll
    for (int nt = 0; nt < 16; nt++)
        #pragma unroll
        for (int v = 0; v < 4; v++) acc[nt][v] = 0.f;
    gemm128_core(smb, PB_A, PB_W, lid, arow, akof, acc);

    {
        const float f0 = (gr0 < N_NODES && g_cnt[gr0] > 0.f) ? 1.f : 0.f;
        const float f1 = (gr1 < N_NODES && g_cnt[gr1] > 0.f) ? 1.f : 0.f;
        #pragma unroll
        for (int nt = 0; nt < 16; nt++) {
            const int c = nt * 8 + qc;
            float t00 = 0.f, t01 = 0.f, t10 = 0.f, t11 = 0.f;
            if (gr0 < N_NODES) {
                float2 p = *(const float2*)(g_P3 + (size_t)gr0 * 128 + c);
                t00 = fmaxf(p.x + acc[nt][0] + f0 * s_b23[c], 0.f);
                t01 = fmaxf(p.y + acc[nt][1] + f0 * s_b23[c + 1], 0.f);
            }
            if (gr1 < N_NODES) {
                float2 p = *(const float2*)(g_P3 + (size_t)gr1 * 128 + c);
                t10 = fmaxf(p.x + acc[nt][2] + f1 * s_b23[c], 0.f);
                t11 = fmaxf(p.y + acc[nt][3] + f1 * s_b23[c + 1], 0.f);
            }
            uint32_t hi0, lo0, hi1, lo1;
            split2(t00, t01, hi0, lo0);
            split2(t10, t11, hi1, lo1);
            const int chunk = (c >> 6) * 16384;
            const int kk2 = (c & 63) * 2;
            *(uint32_t*)(smc + PB_A + chunk + swz(r0 * 128 + kk2)) = hi0;
            *(uint32_t*)(smc + PB_A + chunk + swz(r1 * 128 + kk2)) = hi1;
            *(uint32_t*)(smc + PB_A + 32768 + chunk + swz(r0 * 128 + kk2)) = lo0;
            *(uint32_t*)(smc + PB_A + 32768 + chunk + swz(r1 * 128 + kk2)) = lo1;
        }
    }
    __syncthreads();
    {
        const float4* src = (const float4*)(g_WB + 32768 + 3 * 65536);
        float4* dst = (float4*)smc;
        #pragma unroll
        for (int i = 0; i < 16; i++) dst[tid + 256 * i] = src[tid + 256 * i];
    }
    __syncthreads();
    #pragma unroll
    for (int nt = 0; nt < 16; nt++)
        #pragma unroll
        for (int v = 0; v < 4; v++) acc[nt][v] = 0.f;
    gemm128_core(smb, PB_A, PB_W, lid, arow, akof, acc);
    #pragma unroll
    for (int nt = 0; nt < 16; nt++) {
        const int c = nt * 8 + qc;
        if (gr0 < N_NODES)
            *(float2*)(out + (size_t)gr0 * 128 + c) = make_float2(
                acc[nt][0] + s_b4[c], acc[nt][1] + s_b4[c + 1]);
        if (gr1 < N_NODES)
            *(float2*)(out + (size_t)gr1 * 128 + c) = make_float2(
                acc[nt][2] + s_b4[c], acc[nt][3] + s_b4[c + 1]);
    }
}

// ---------------------------------------------------------------------------
// Edge kernel: 256 threads, 2 CTAs/SM, 64-edge tiles. Warp = 32 rows x 32
// cols (8 warps = 2 row-groups x 4 col-quarters). Vs R10's 16x64: B-operand
// redundancy 4 -> 2, A-redundancy 2 -> 4; per-tile L1 traffic 160KB -> 128KB
// and LDSM count 40 -> 32 per warp, at IDENTICAL register footprint
// (acc[2][4][4] = 32 floats). Double-buffered A staging, P prefetch (2 rows),
// one __syncthreads per tile.
// SMEM: [0,16K) B1hi | 16K B1lo | 32K A0hi | 40K A0lo | 48K A1hi | 56K A1lo
//       | 64K idx (2 x 128 ints)
#define SM_B1HI 0
#define SM_B1LO 16384
#define SM_A    32768
#define SM_IDX  65536
#define EDGE_SMEM_BYTES (65536 + 1280)
#define EDGE_THREADS 256
#define TILE_E 64

__global__ __launch_bounds__(EDGE_THREADS, 2)
void edge_kernel_mma(const float* __restrict__ ea, const int* __restrict__ eidx,
                     int E, int ntiles) {
    extern __shared__ char smc[];
    const uint32_t smb = smem_u32(smc);
    const int tid = threadIdx.x;
    const int wid = tid >> 5;
    const int lid = tid & 31;

    {   // weights once (32 KB)
        const float4* src = (const float4*)g_WB;
        float4* dst = (float4*)smc;
        for (int i = tid; i < 2048; i += EDGE_THREADS) dst[i] = src[i];
    }

    // staging lane geometry (4 threads/row, 16 floats each; 64 rows)
    const int st_r = tid >> 2;
    const int st_q = tid & 3;

    // MMA lane geometry: 2 row-groups(32) x 4 col-quarters(32)
    const int rgroup = (wid >> 2) * 32;
    const int cq     = (wid & 3) * 32;
    const int qr = lid >> 2;
    const int am = lid >> 3;
    const int arowb = ((am & 1) << 3) + (lid & 7);   // row within 16-strip
    const int akof = (am >> 1) << 4;
    const int ntoff = lid >> 4;
    const int brow = lid & 7;
    const int bkof = ((lid >> 3) & 1) << 4;
    // epilogue shuffle geometry
    const int cboff = (lid & 2) ? 4 : 0;
    const bool evenlane = ((lid & 1) == 0);
    // per-strip epilogue rows: strip s covers rows rgroup+s*16 .. +15
    const int myrow0 = rgroup + (evenlane ? qr : qr + 8);
    const int myrow1 = myrow0 + 16;

    // ---- stage helper: 64-edge tile into buffer q ----
    auto stage = [&](int tile, int q) {
        const int e0s = tile * TILE_E;
        int* rowq = (int*)(smc + SM_IDX) + q * 128;
        int* colq = rowq + 64;
        if (tid < 64) {
            int e = e0s + tid;
            rowq[tid] = (e < E) ? eidx[e] : 0;
        } else if (tid < 128) {
            int t = tid - 64, e = e0s + t;
            colq[t] = (e < E) ? eidx[(size_t)E + e] : 0;
        }
        const int e = e0s + st_r;
        const bool valid = e < E;
        const float* src = ea + (size_t)e * EF + st_q * 16;
        const uint32_t abase = (uint32_t)(SM_A + q * 16384);
        #pragma unroll
        for (int j = 0; j < 2; j++) {
            float4 v0 = valid ? *(const float4*)(src + j * 8)
                              : make_float4(0.f, 0.f, 0.f, 0.f);
            float4 v1 = valid ? *(const float4*)(src + j * 8 + 4)
                              : make_float4(0.f, 0.f, 0.f, 0.f);
            uint4 hi, lo;
            split8(v0, v1, hi, lo);
            uint32_t off = swz(st_r * 128 + st_q * 32 + j * 16);
            *(uint4*)(smc + abase + off) = hi;
            *(uint4*)(smc + abase + 8192 + off) = lo;
        }
    };

    if (blockIdx.x < ntiles) stage(blockIdx.x, 0);
    __syncthreads();

    int p = 0;
    for (int tile = blockIdx.x; tile < ntiles; tile += gridDim.x, p ^= 1) {
        const int e0 = tile * TILE_E;
        const int* rowp = (const int*)(smc + SM_IDX) + p * 128;
        const int* colp = rowp + 64;
        const uint32_t aoff = (uint32_t)(SM_A + p * 16384);

        // ---- prefetch both P-row quarters to L1 (overlaps GEMM) ----
        const float* Pbase0 = g_P + (size_t)colp[myrow0] * 128 + cq;
        const float* Pbase1 = g_P + (size_t)colp[myrow1] * 128 + cq;
        asm volatile("prefetch.global.L1 [%0];" :: "l"(Pbase0));
        asm volatile("prefetch.global.L1 [%0];" :: "l"(Pbase1));

        // ---- GEMM1: acc[strip][nt][4], 32x32 footprint, K=64 ----
        float acc[2][4][4];
        #pragma unroll
        for (int s = 0; s < 2; s++)
            #pragma unroll
            for (int nt = 0; nt < 4; nt++)
                #pragma unroll
                for (int v = 0; v < 4; v++) acc[s][nt][v] = 0.f;
        #pragma unroll
        for (int kt = 0; kt < 4; kt++) {
            const int kb = kt * 32;
            uint32_t ahi[2][4], alo[2][4];
            #pragma unroll
            for (int s = 0; s < 2; s++) {
                const int arow = rgroup + s * 16 + arowb;
                ldsm_x4(ahi[s], smb + aoff + swz(arow * 128 + kb + akof));
                ldsm_x4(alo[s], smb + aoff + 8192 + swz(arow * 128 + kb + akof));
            }
            #pragma unroll
            for (int pr = 0; pr < 2; pr++) {
                const int ntg = (cq >> 3) + pr * 2 + ntoff;
                uint32_t bo = swz((ntg * 8 + brow) * 128 + kb + bkof);
                uint32_t bh[4], bl[4];
                ldsm_x4(bh, smb + SM_B1HI + bo);
                ldsm_x4(bl, smb + SM_B1LO + bo);
                #pragma unroll
                for (int s = 0; s < 2; s++) {
                    mma_bf16(acc[s][pr * 2],     ahi[s], bh);
                    mma_bf16(acc[s][pr * 2],     ahi[s], bl);
                    mma_bf16(acc[s][pr * 2],     alo[s], bh);
                    mma_bf16(acc[s][pr * 2 + 1], ahi[s], bh + 2);
                    mma_bf16(acc[s][pr * 2 + 1], ahi[s], bl + 2);
                    mma_bf16(acc[s][pr * 2 + 1], alo[s], bh + 2);
                }
            }
        }

        // ---- stage NEXT tile into the other buffer (overlaps epilogue) ----
        const int nxt = tile + gridDim.x;
        if (nxt < ntiles) stage(nxt, 1 - p);

        // ---- epilogue per strip: shuffle; h = relu(D1 + P); RED.F32X4 ----
        #pragma unroll
        for (int s = 0; s < 2; s++) {
            const int myrow = s ? myrow1 : myrow0;
            const bool valid = (e0 + myrow < E);
            const float* Pn = (s ? Pbase1 : Pbase0) + cboff;
            float* Sn = g_sums + (size_t)rowp[myrow] * 128 + cq + cboff;
            #pragma unroll
            for (int nt = 0; nt < 4; nt++) {
                float sA = evenlane ? acc[s][nt][2] : acc[s][nt][0];
                float sB = evenlane ? acc[s][nt][3] : acc[s][nt][1];
                float rA = __shfl_xor_sync(0xFFFFFFFFu, sA, 1);
                float rB = __shfl_xor_sync(0xFFFFFFFFu, sB, 1);
                float4 v = evenlane
                    ? make_float4(acc[s][nt][0], acc[s][nt][1], rA, rB)
                    : make_float4(rA, rB, acc[s][nt][2], acc[s][nt][3]);
                if (valid) {
                    float4 pv = *(const float4*)(Pn + nt * 8);
                    v.x = fmaxf(v.x + pv.x, 0.f);
                    v.y = fmaxf(v.y + pv.y, 0.f);
                    v.z = fmaxf(v.z + pv.z, 0.f);
                    v.w = fmaxf(v.w + pv.w, 0.f);
                    atomicAdd((float4*)(Sn + nt * 8), v);
                }
            }
        }
        if (tid < 64 && e0 + tid < E) atomicAdd(&g_cnt[rowp[tid]], 1.0f);

        __syncthreads();   // buffer 1-p fully staged; buffer p free to rewrite
    }
}

// ---------------------------------------------------------------------------
extern "C" void kernel_launch(void* const* d_in, const int* in_sizes, int n_in,
                              void* d_out, int out_size) {
    const float* node_feat = (const float*)d_in[0];
    const int*   eidx      = (const int*)d_in[1];   // int32 (JAX x64 disabled)
    const float* ea        = (const float*)d_in[2];
    const float* W1 = (const float*)d_in[3];
    const float* b1 = (const float*)d_in[4];
    const float* W2 = (const float*)d_in[5];
    const float* b2 = (const float*)d_in[6];
    const float* W3 = (const float*)d_in[7];
    const float* b3 = (const float*)d_in[8];
    const float* W4 = (const float*)d_in[9];
    const float* b4 = (const float*)d_in[10];
    float* out = (float*)d_out;

    const int E = in_sizes[1] / 2;
    const int NBN = (N_NODES + 127) / 128;      // 391
    const int NTE = (E + TILE_E - 1) / TILE_E;  // 25000

    cudaFuncSetAttribute(pre_both_kernel,
                         cudaFuncAttributeMaxDynamicSharedMemorySize, PB_SMEM);
    cudaFuncSetAttribute(node_fused_kernel,
                         cudaFuncAttributeMaxDynamicSharedMemorySize, PB_SMEM);
    cudaFuncSetAttribute(edge_kernel_mma,
                         cudaFuncAttributeMaxDynamicSharedMemorySize, EDGE_SMEM_BYTES);

    zero_kernel<<<1024, 256>>>();
    prep1_kernel<<<129, 128>>>(W2, W3, b2);
    prep2_kernel<<<64, 256>>>(W1, W3, W4);
    pre_both_kernel<<<NBN, 256, PB_SMEM>>>(node_feat, b1, b3);
    edge_kernel_mma<<<296, EDGE_THREADS, EDGE_SMEM_BYTES>>>(ea, eidx, E, NTE);
    node_fused_kernel<<<NBN, 256, PB_SMEM>>>(b4, out);
}

// round 14
// speedup vs baseline: 1.1151x; 1.0679x over previous
#include <cuda_runtime.h>
#include <cuda_bf16.h>
#include <cuda_fp16.h>
#include <cstdint>

#define N_NODES 50000
#define HID 128
#define EF 64

// ---------------------------------------------------------------------------
// Scratch (device globals — allocation-free per harness rules)
__device__ float g_P   [(size_t)N_NODES * HID];   // node_feat@W1_top+b1
__device__ float g_P3  [(size_t)N_NODES * HID];   // node_feat@W3_top+b3
__device__ float g_sums[(size_t)N_NODES * HID];   // scatter-add of relu-h
__device__ float g_cnt [N_NODES];
__device__ float g_W23 [128 * 128];               // W2 @ W3_bot (fp32)
__device__ float g_b23 [128];                     // b2 @ W3_bot
// Weight images, [N][K] K-major 128B rows, SW128-swizzled.
// [0,16K) B1 fp16 (edge)  |  [16K,32K) unused  |  then 4 node bf16 hi/lo
// images x 64KB each. widx: 0=W1_top 1=W3_top 2=W23 3=W4
__device__ __align__(16) unsigned char g_WB[32768 + 4 * 65536];

__device__ __forceinline__ uint32_t smem_u32(const void* p) {
    uint32_t a;
    asm("{ .reg .u64 t; cvta.to.shared.u64 t, %1; cvt.u32.u64 %0, t; }"
        : "=r"(a) : "l"(p));
    return a;
}
__device__ __forceinline__ uint32_t swz(uint32_t b) { return b ^ ((b >> 3) & 0x70); }

__device__ __forceinline__ void ldsm_x4(uint32_t* r, uint32_t addr) {
    asm volatile("ldmatrix.sync.aligned.m8n8.x4.shared.b16 {%0,%1,%2,%3}, [%4];"
                 : "=r"(r[0]), "=r"(r[1]), "=r"(r[2]), "=r"(r[3]) : "r"(addr));
}
__device__ __forceinline__ void mma_bf16(float* d, const uint32_t* a, const uint32_t* b) {
    asm volatile("mma.sync.aligned.m16n8k16.row.col.f32.bf16.bf16.f32 "
                 "{%0,%1,%2,%3}, {%4,%5,%6,%7}, {%8,%9}, {%0,%1,%2,%3};"
                 : "+f"(d[0]), "+f"(d[1]), "+f"(d[2]), "+f"(d[3])
                 : "r"(a[0]), "r"(a[1]), "r"(a[2]), "r"(a[3]), "r"(b[0]), "r"(b[1]));
}
__device__ __forceinline__ void mma_f16(float* d, const uint32_t* a, const uint32_t* b) {
    asm volatile("mma.sync.aligned.m16n8k16.row.col.f32.f16.f16.f32 "
                 "{%0,%1,%2,%3}, {%4,%5,%6,%7}, {%8,%9}, {%0,%1,%2,%3};"
                 : "+f"(d[0]), "+f"(d[1]), "+f"(d[2]), "+f"(d[3])
                 : "r"(a[0]), "r"(a[1]), "r"(a[2]), "r"(a[3]), "r"(b[0]), "r"(b[1]));
}
__device__ __forceinline__ uint32_t pack_bf16x2(float x, float y) {
    __nv_bfloat162 p = {__float2bfloat16(x), __float2bfloat16(y)};
    return *(uint32_t*)&p;
}
__device__ __forceinline__ void split2(float x, float y, uint32_t& hi, uint32_t& lo) {
    __nv_bfloat16 hx = __float2bfloat16(x), hy = __float2bfloat16(y);
    __nv_bfloat162 ph = {hx, hy};
    hi = *(uint32_t*)&ph;
    lo = pack_bf16x2(x - __bfloat162float(hx), y - __bfloat162float(hy));
}
__device__ __forceinline__ void split8(float4 v0, float4 v1, uint4& hi, uint4& lo) {
    split2(v0.x, v0.y, hi.x, lo.x);
    split2(v0.z, v0.w, hi.y, lo.y);
    split2(v1.x, v1.y, hi.z, lo.z);
    split2(v1.z, v1.w, hi.w, lo.w);
}
// fp16 hi/lo split (A error ~2^-22)
__device__ __forceinline__ void split2h(float x, float y, uint32_t& hi, uint32_t& lo) {
    __half hx = __float2half(x), hy = __float2half(y);
    __half2 ph = {hx, hy};
    hi = *(uint32_t*)&ph;
    __half2 pl = {__float2half(x - __half2float(hx)),
                  __float2half(y - __half2float(hy))};
    lo = *(uint32_t*)&pl;
}
__device__ __forceinline__ void split8h(float4 v0, float4 v1, uint4& hi, uint4& lo) {
    split2h(v0.x, v0.y, hi.x, lo.x);
    split2h(v0.z, v0.w, hi.y, lo.y);
    split2h(v1.x, v1.y, hi.z, lo.z);
    split2h(v1.z, v1.w, hi.w, lo.w);
}

// Shared K=128 bf16x3 GEMM core with x4 B-operand ldmatrix (256-thr kernels).
__device__ __forceinline__ void gemm128_core(
    uint32_t smb, uint32_t aoff, uint32_t woff, int lid,
    int arow, int akof, float acc[16][4]) {
    const int ntoff = lid >> 4;
    const int brow = lid & 7;
    const int bkof = ((lid >> 3) & 1) << 4;
    #pragma unroll
    for (int kt = 0; kt < 8; kt++) {
        const int chunk = (kt >> 2) * 16384;
        const int kb = (kt & 3) * 32;
        uint32_t ahi[4], alo[4];
        ldsm_x4(ahi, smb + aoff + chunk + swz(arow * 128 + kb + akof));
        ldsm_x4(alo, smb + aoff + 32768 + chunk + swz(arow * 128 + kb + akof));
        #pragma unroll
        for (int nt = 0; nt < 16; nt += 2) {
            uint32_t bo = swz(((nt + ntoff) * 8 + brow) * 128 + kb + bkof);
            uint32_t bh[4], bl[4];
            ldsm_x4(bh, smb + woff + chunk + bo);
            ldsm_x4(bl, smb + woff + 32768 + chunk + bo);
            mma_bf16(acc[nt],     ahi, bh);
            mma_bf16(acc[nt],     ahi, bl);
            mma_bf16(acc[nt],     alo, bh);
            mma_bf16(acc[nt + 1], ahi, bh + 2);
            mma_bf16(acc[nt + 1], ahi, bl + 2);
            mma_bf16(acc[nt + 1], alo, bh + 2);
        }
    }
}

// ---------------------------------------------------------------------------
__global__ void zero_kernel() {
    const size_t total4 = (size_t)N_NODES * HID / 4;
    float4* s = (float4*)g_sums;
    const float4 z = make_float4(0.f, 0.f, 0.f, 0.f);
    for (size_t i = (size_t)blockIdx.x * blockDim.x + threadIdx.x; i < total4;
         i += (size_t)gridDim.x * blockDim.x)
        s[i] = z;
    for (int i = blockIdx.x * blockDim.x + threadIdx.x; i < N_NODES;
         i += gridDim.x * blockDim.x)
        g_cnt[i] = 0.f;
}

// ---------------------------------------------------------------------------
// W23 = W2 @ W3[128:256], b23 = b2 @ W3[128:256]
__global__ void prep1_kernel(const float* __restrict__ W2,
                             const float* __restrict__ W3,
                             const float* __restrict__ b2) {
    __shared__ float srow[128];
    const int r = blockIdx.x;
    const int c = threadIdx.x;
    srow[c] = (r < 128) ? W2[r * 128 + c] : b2[c];
    __syncthreads();
    float acc = 0.f;
    #pragma unroll 4
    for (int k = 0; k < 128; k++)
        acc += srow[k] * W3[(128 + k) * 128 + c];
    if (r < 128) g_W23[r * 128 + c] = acc;
    else         g_b23[c] = acc;
}

// ---------------------------------------------------------------------------
__global__ void prep2_kernel(const float* __restrict__ W1,
                             const float* __restrict__ W3,
                             const float* __restrict__ W4) {
    const int tid = blockIdx.x * blockDim.x + threadIdx.x;
    const int nth = gridDim.x * blockDim.x;
    for (int i = tid; i < 128 * 64; i += nth) {   // edge B1 fp16 (single image)
        int n = i >> 6, k = i & 63;
        float v = W1[(128 + k) * 128 + n];
        uint32_t off = swz(n * 128 + k * 2);
        *(__half*)(g_WB + off) = __float2half(v);
    }
    for (int i = tid; i < 4 * 128 * 128; i += nth) {  // node weights (bf16 hi/lo)
        int widx = i >> 14, j = i & 16383;
        int n = j >> 7, k = j & 127;
        float v;
        if      (widx == 0) v = W1[k * 128 + n];
        else if (widx == 1) v = W3[k * 128 + n];
        else if (widx == 2) v = g_W23[k * 128 + n];
        else                v = W4[k * 128 + n];
        __nv_bfloat16 h = __float2bfloat16(v);
        __nv_bfloat16 l = __float2bfloat16(v - __bfloat162float(h));
        int c = k >> 6, kk = k & 63;
        uint32_t off = swz(n * 128 + kk * 2);
        unsigned char* base = g_WB + 32768 + widx * 65536;
        *(__nv_bfloat16*)(base + c * 16384 + off)         = h;
        *(__nv_bfloat16*)(base + 32768 + c * 16384 + off) = l;
    }
}

// ---------------------------------------------------------------------------
// pre_both: stage node_feat once; P = nf@W1t + b1; P3 = nf@W3t + b3.
#define PB_W 0
#define PB_A 65536
#define PB_BIAS 131072
#define PB_SMEM (131072 + 1024)

__global__ __launch_bounds__(256, 1)
void pre_both_kernel(const float* __restrict__ A, const float* __restrict__ b1,
                     const float* __restrict__ b3) {
    extern __shared__ char smc[];
    const uint32_t smb = smem_u32(smc);
    const int tid = threadIdx.x;
    const int wid = tid >> 5;
    const int lid = tid & 31;
    float* s_b1 = (float*)(smc + PB_BIAS);
    float* s_b3 = s_b1 + 128;

    {
        const float4* src = (const float4*)(g_WB + 32768);
        float4* dst = (float4*)smc;
        #pragma unroll
        for (int i = 0; i < 16; i++) dst[tid + 256 * i] = src[tid + 256 * i];
    }
    if (tid < 128) { s_b1[tid] = b1[tid]; s_b3[tid] = b3[tid]; }

    const int m0 = blockIdx.x * 128;
    {
        const int r = tid >> 1;
        const int chunk = tid & 1;
        const int gr = m0 + r;
        const bool valid = gr < N_NODES;
        const float* src = A + (size_t)gr * 128 + chunk * 64;
        #pragma unroll
        for (int j = 0; j < 8; j++) {
            float4 v0 = valid ? *(const float4*)(src + j * 8)
                              : make_float4(0.f, 0.f, 0.f, 0.f);
            float4 v1 = valid ? *(const float4*)(src + j * 8 + 4)
                              : make_float4(0.f, 0.f, 0.f, 0.f);
            uint4 hi, lo;
            split8(v0, v1, hi, lo);
            uint32_t off = swz(r * 128 + j * 16);
            *(uint4*)(smc + PB_A + chunk * 16384 + off) = hi;
            *(uint4*)(smc + PB_A + 32768 + chunk * 16384 + off) = lo;
        }
    }
    __syncthreads();

    const int wr0 = wid * 16;
    const int qr = lid >> 2, qc = (lid & 3) * 2;
    const int r0 = wr0 + qr, r1 = r0 + 8;
    const int am = lid >> 3;
    const int arow = wr0 + ((am & 1) << 3) + (lid & 7);
    const int akof = (am >> 1) << 4;
    const int gr0 = m0 + r0, gr1 = m0 + r1;

    float acc[16][4];
    #pragma unroll
    for (int nt = 0; nt < 16; nt++)
        #pragma unroll
        for (int v = 0; v < 4; v++) acc[nt][v] = 0.f;
    gemm128_core(smb, PB_A, PB_W, lid, arow, akof, acc);
    #pragma unroll
    for (int nt = 0; nt < 16; nt++) {
        const int c = nt * 8 + qc;
        if (gr0 < N_NODES)
            *(float2*)(g_P + (size_t)gr0 * 128 + c) = make_float2(
                acc[nt][0] + s_b1[c], acc[nt][1] + s_b1[c + 1]);
        if (gr1 < N_NODES)
            *(float2*)(g_P + (size_t)gr1 * 128 + c) = make_float2(
                acc[nt][2] + s_b1[c], acc[nt][3] + s_b1[c + 1]);
    }
    __syncthreads();
    {
        const float4* src = (const float4*)(g_WB + 32768 + 65536);
        float4* dst = (float4*)smc;
        #pragma unroll
        for (int i = 0; i < 16; i++) dst[tid + 256 * i] = src[tid + 256 * i];
    }
    __syncthreads();
    #pragma unroll
    for (int nt = 0; nt < 16; nt++)
        #pragma unroll
        for (int v = 0; v < 4; v++) acc[nt][v] = 0.f;
    gemm128_core(smb, PB_A, PB_W, lid, arow, akof, acc);
    #pragma unroll
    for (int nt = 0; nt < 16; nt++) {
        const int c = nt * 8 + qc;
        if (gr0 < N_NODES)
            *(float2*)(g_P3 + (size_t)gr0 * 128 + c) = make_float2(
                acc[nt][0] + s_b3[c], acc[nt][1] + s_b3[c + 1]);
        if (gr1 < N_NODES)
            *(float2*)(g_P3 + (size_t)gr1 * 128 + c) = make_float2(
                acc[nt][2] + s_b3[c], acc[nt][3] + s_b3[c + 1]);
    }
}

// ---------------------------------------------------------------------------
// node_fused: mean = sums/max(cnt,1); T = relu(P3 + mean@W23 + flag*b23);
// out = T@W4 + b4.
__global__ __launch_bounds__(256, 1)
void node_fused_kernel(const float* __restrict__ b4, float* __restrict__ out) {
    extern __shared__ char smc[];
    const uint32_t smb = smem_u32(smc);
    const int tid = threadIdx.x;
    const int wid = tid >> 5;
    const int lid = tid & 31;
    float* s_b23 = (float*)(smc + PB_BIAS);
    float* s_b4  = s_b23 + 128;

    {
        const float4* src = (const float4*)(g_WB + 32768 + 2 * 65536);
        float4* dst = (float4*)smc;
        #pragma unroll
        for (int i = 0; i < 16; i++) dst[tid + 256 * i] = src[tid + 256 * i];
    }
    if (tid < 128) { s_b23[tid] = g_b23[tid]; s_b4[tid] = b4[tid]; }

    const int m0 = blockIdx.x * 128;
    {
        const int r = tid >> 1;
        const int chunk = tid & 1;
        const int gr = m0 + r;
        const bool valid = gr < N_NODES;
        float s = valid ? 1.f / fmaxf(g_cnt[gr], 1.f) : 0.f;
        const float* src = g_sums + (size_t)gr * 128 + chunk * 64;
        #pragma unroll
        for (int j = 0; j < 8; j++) {
            float4 v0 = valid ? *(const float4*)(src + j * 8)
                              : make_float4(0.f, 0.f, 0.f, 0.f);
            float4 v1 = valid ? *(const float4*)(src + j * 8 + 4)
                              : make_float4(0.f, 0.f, 0.f, 0.f);
            v0.x *= s; v0.y *= s; v0.z *= s; v0.w *= s;
            v1.x *= s; v1.y *= s; v1.z *= s; v1.w *= s;
            uint4 hi, lo;
            split8(v0, v1, hi, lo);
            uint32_t off = swz(r * 128 + j * 16);
            *(uint4*)(smc + PB_A + chunk * 16384 + off) = hi;
            *(uint4*)(smc + PB_A + 32768 + chunk * 16384 + off) = lo;
        }
    }
    __syncthreads();

    const int wr0 = wid * 16;
    const int qr = lid >> 2, qc = (lid & 3) * 2;
    const int r0 = wr0 + qr, r1 = r0 + 8;
    const int am = lid >> 3;
    const int arow = wr0 + ((am & 1) << 3) + (lid & 7);
    const int akof = (am >> 1) << 4;
    const int gr0 = m0 + r0, gr1 = m0 + r1;

    float acc[16][4];
    #pragma unroll
    for (int nt = 0; nt < 16; nt++)
        #pragma unroll
        for (int v = 0; v < 4; v++) acc[nt][v] = 0.f;
    gemm128_core(smb, PB_A, PB_W, lid, arow, akof, acc);

    {
        const float f0 = (gr0 < N_NODES && g_cnt[gr0] > 0.f) ? 1.f : 0.f;
        const float f1 = (gr1 < N_NODES && g_cnt[gr1] > 0.f) ? 1.f : 0.f;
        #pragma unroll
        for (int nt = 0; nt < 16; nt++) {
            const int c = nt * 8 + qc;
            float t00 = 0.f, t01 = 0.f, t10 = 0.f, t11 = 0.f;
            if (gr0 < N_NODES) {
                float2 p = *(const float2*)(g_P3 + (size_t)gr0 * 128 + c);
                t00 = fmaxf(p.x + acc[nt][0] + f0 * s_b23[c], 0.f);
                t01 = fmaxf(p.y + acc[nt][1] + f0 * s_b23[c + 1], 0.f);
            }
            if (gr1 < N_NODES) {
                float2 p = *(const float2*)(g_P3 + (size_t)gr1 * 128 + c);
                t10 = fmaxf(p.x + acc[nt][2] + f1 * s_b23[c], 0.f);
                t11 = fmaxf(p.y + acc[nt][3] + f1 * s_b23[c + 1], 0.f);
            }
            uint32_t hi0, lo0, hi1, lo1;
            split2(t00, t01, hi0, lo0);
            split2(t10, t11, hi1, lo1);
            const int chunk = (c >> 6) * 16384;
            const int kk2 = (c & 63) * 2;
            *(uint32_t*)(smc + PB_A + chunk + swz(r0 * 128 + kk2)) = hi0;
            *(uint32_t*)(smc + PB_A + chunk + swz(r1 * 128 + kk2)) = hi1;
            *(uint32_t*)(smc + PB_A + 32768 + chunk + swz(r0 * 128 + kk2)) = lo0;
            *(uint32_t*)(smc + PB_A + 32768 + chunk + swz(r1 * 128 + kk2)) = lo1;
        }
    }
    __syncthreads();
    {
        const float4* src = (const float4*)(g_WB + 32768 + 3 * 65536);
        float4* dst = (float4*)smc;
        #pragma unroll
        for (int i = 0; i < 16; i++) dst[tid + 256 * i] = src[tid + 256 * i];
    }
    __syncthreads();
    #pragma unroll
    for (int nt = 0; nt < 16; nt++)
        #pragma unroll
        for (int v = 0; v < 4; v++) acc[nt][v] = 0.f;
    gemm128_core(smb, PB_A, PB_W, lid, arow, akof, acc);
    #pragma unroll
    for (int nt = 0; nt < 16; nt++) {
        const int c = nt * 8 + qc;
        if (gr0 < N_NODES)
            *(float2*)(out + (size_t)gr0 * 128 + c) = make_float2(
                acc[nt][0] + s_b4[c], acc[nt][1] + s_b4[c + 1]);
        if (gr1 < N_NODES)
            *(float2*)(out + (size_t)gr1 * 128 + c) = make_float2(
                acc[nt][2] + s_b4[c], acc[nt][3] + s_b4[c + 1]);
    }
}

// ---------------------------------------------------------------------------
// Edge kernel: 256 threads, 2 CTAs/SM, 64-edge tiles (R10 geometry), fp16
// 2-term emulation: D1 = (Ahi + Alo) @ B1(fp16). 2 MMAs per (kt,pair) vs 3
// for bf16x3 — edge tensor work drops 33%. A split fp16 hi/lo (err 2^-22);
// B quantization err 2^-11 -> output rel err ~1e-4, inside the 1e-3 budget.
// Double-buffered A staging, P prefetch, one __syncthreads per tile.
// SMEM: [0,16K) B1 fp16 | 16K A0hi | 24K A0lo | 32K A1hi | 40K A1lo
//       | 48K idx (2 x 128 ints)
#define SM_B1   0
#define SM_A    16384
#define SM_IDX  49152
#define EDGE_SMEM_BYTES (49152 + 1280)
#define EDGE_THREADS 256
#define TILE_E 64

__global__ __launch_bounds__(EDGE_THREADS, 2)
void edge_kernel_mma(const float* __restrict__ ea, const int* __restrict__ eidx,
                     int E, int ntiles) {
    extern __shared__ char smc[];
    const uint32_t smb = smem_u32(smc);
    const int tid = threadIdx.x;
    const int wid = tid >> 5;
    const int lid = tid & 31;

    {   // B1 fp16 image once (16 KB)
        const float4* src = (const float4*)g_WB;
        float4* dst = (float4*)smc;
        for (int i = tid; i < 1024; i += EDGE_THREADS) dst[i] = src[i];
    }

    // staging lane geometry (4 threads/row, 16 floats each; 64 rows)
    const int st_r = tid >> 2;
    const int st_q = tid & 3;

    // MMA lane geometry: 4 row strips x 2 col halves
    const int rstrip = (wid >> 1) * 16;
    const int chalf  = (wid & 1) * 64;
    const int qr = lid >> 2;
    const int r0 = rstrip + qr, r1 = r0 + 8;
    const int am = lid >> 3;
    const int arow = rstrip + ((am & 1) << 3) + (lid & 7);
    const int akof = (am >> 1) << 4;
    const int ntoff = lid >> 4;
    const int brow = lid & 7;
    const int bkof = ((lid >> 3) & 1) << 4;
    // epilogue shuffle geometry
    const int cboff = (lid & 2) ? 4 : 0;
    const bool evenlane = ((lid & 1) == 0);
    const int myrow = evenlane ? r0 : r1;

    // ---- stage helper: 64-edge tile into buffer q (fp16 hi/lo) ----
    auto stage = [&](int tile, int q) {
        const int e0s = tile * TILE_E;
        int* rowq = (int*)(smc + SM_IDX) + q * 128;
        int* colq = rowq + 64;
        if (tid < 64) {
            int e = e0s + tid;
            rowq[tid] = (e < E) ? eidx[e] : 0;
        } else if (tid < 128) {
            int t = tid - 64, e = e0s + t;
            colq[t] = (e < E) ? eidx[(size_t)E + e] : 0;
        }
        const int e = e0s + st_r;
        const bool valid = e < E;
        const float* src = ea + (size_t)e * EF + st_q * 16;
        const uint32_t abase = (uint32_t)(SM_A + q * 16384);
        #pragma unroll
        for (int j = 0; j < 2; j++) {
            float4 v0 = valid ? *(const float4*)(src + j * 8)
                              : make_float4(0.f, 0.f, 0.f, 0.f);
            float4 v1 = valid ? *(const float4*)(src + j * 8 + 4)
                              : make_float4(0.f, 0.f, 0.f, 0.f);
            uint4 hi, lo;
            split8h(v0, v1, hi, lo);
            uint32_t off = swz(st_r * 128 + st_q * 32 + j * 16);
            *(uint4*)(smc + abase + off) = hi;
            *(uint4*)(smc + abase + 8192 + off) = lo;
        }
    };

    if (blockIdx.x < ntiles) stage(blockIdx.x, 0);
    __syncthreads();

    int p = 0;
    for (int tile = blockIdx.x; tile < ntiles; tile += gridDim.x, p ^= 1) {
        const int e0 = tile * TILE_E;
        const int* rowp = (const int*)(smc + SM_IDX) + p * 128;
        const int* colp = rowp + 64;
        const uint32_t aoff = (uint32_t)(SM_A + p * 16384);

        // ---- prefetch this thread's P-row segment to L1 (overlaps GEMM) ----
        const int srcnode = colp[myrow];
        const float* Pbase = g_P + (size_t)srcnode * 128 + chalf;
        asm volatile("prefetch.global.L1 [%0];" :: "l"(Pbase));
        asm volatile("prefetch.global.L1 [%0];" :: "l"(Pbase + 32));

        // ---- GEMM1: 8 nt per warp; fp16 2-term ----
        float acc[8][4];
        #pragma unroll
        for (int nt = 0; nt < 8; nt++)
            #pragma unroll
            for (int v = 0; v < 4; v++) acc[nt][v] = 0.f;
        #pragma unroll
        for (int kt = 0; kt < 4; kt++) {
            const int kb = kt * 32;
            uint32_t ahi[4], alo[4];
            ldsm_x4(ahi, smb + aoff + swz(arow * 128 + kb + akof));
            ldsm_x4(alo, smb + aoff + 8192 + swz(arow * 128 + kb + akof));
            #pragma unroll
            for (int nt = 0; nt < 8; nt += 2) {
                const int ntg = (chalf >> 3) + nt + ntoff;
                uint32_t bo = swz((ntg * 8 + brow) * 128 + kb + bkof);
                uint32_t bh[4];
                ldsm_x4(bh, smb + SM_B1 + bo);
                mma_f16(acc[nt],     ahi, bh);
                mma_f16(acc[nt],     alo, bh);
                mma_f16(acc[nt + 1], ahi, bh + 2);
                mma_f16(acc[nt + 1], alo, bh + 2);
            }
        }

        // ---- stage NEXT tile into the other buffer (overlaps epilogue) ----
        const int nxt = tile + gridDim.x;
        if (nxt < ntiles) stage(nxt, 1 - p);

        // ---- epilogue: shuffle to float4; h = relu(D1 + P[col]); RED.F32X4
        {
            const bool valid = (e0 + myrow < E);
            const float* Pn = Pbase + cboff;
            float* Sn = g_sums + (size_t)rowp[myrow] * 128 + chalf + cboff;
            #pragma unroll
            for (int nt = 0; nt < 8; nt++) {
                float sA = evenlane ? acc[nt][2] : acc[nt][0];
                float sB = evenlane ? acc[nt][3] : acc[nt][1];
                float rA = __shfl_xor_sync(0xFFFFFFFFu, sA, 1);
                float rB = __shfl_xor_sync(0xFFFFFFFFu, sB, 1);
                float4 v = evenlane
                    ? make_float4(acc[nt][0], acc[nt][1], rA, rB)
                    : make_float4(rA, rB, acc[nt][2], acc[nt][3]);
                if (valid) {
                    float4 pv = *(const float4*)(Pn + nt * 8);
                    v.x = fmaxf(v.x + pv.x, 0.f);
                    v.y = fmaxf(v.y + pv.y, 0.f);
                    v.z = fmaxf(v.z + pv.z, 0.f);
                    v.w = fmaxf(v.w + pv.w, 0.f);
                    atomicAdd((float4*)(Sn + nt * 8), v);
                }
            }
        }
        if (tid < 64 && e0 + tid < E) atomicAdd(&g_cnt[rowp[tid]], 1.0f);

        __syncthreads();   // buffer 1-p fully staged; buffer p free to rewrite
    }
}

// ---------------------------------------------------------------------------
extern "C" void kernel_launch(void* const* d_in, const int* in_sizes, int n_in,
                              void* d_out, int out_size) {
    const float* node_feat = (const float*)d_in[0];
    const int*   eidx      = (const int*)d_in[1];   // int32 (JAX x64 disabled)
    const float* ea        = (const float*)d_in[2];
    const float* W1 = (const float*)d_in[3];
    const float* b1 = (const float*)d_in[4];
    const float* W2 = (const float*)d_in[5];
    const float* b2 = (const float*)d_in[6];
    const float* W3 = (const float*)d_in[7];
    const float* b3 = (const float*)d_in[8];
    const float* W4 = (const float*)d_in[9];
    const float* b4 = (const float*)d_in[10];
    float* out = (float*)d_out;

    const int E = in_sizes[1] / 2;
    const int NBN = (N_NODES + 127) / 128;      // 391
    const int NTE = (E + TILE_E - 1) / TILE_E;  // 25000

    cudaFuncSetAttribute(pre_both_kernel,
                         cudaFuncAttributeMaxDynamicSharedMemorySize, PB_SMEM);
    cudaFuncSetAttribute(node_fused_kernel,
                         cudaFuncAttributeMaxDynamicSharedMemorySize, PB_SMEM);
    cudaFuncSetAttribute(edge_kernel_mma,
                         cudaFuncAttributeMaxDynamicSharedMemorySize, EDGE_SMEM_BYTES);

    zero_kernel<<<1024, 256>>>();
    prep1_kernel<<<129, 128>>>(W2, W3, b2);
    prep2_kernel<<<64, 256>>>(W1, W3, W4);
    pre_both_kernel<<<NBN, 256, PB_SMEM>>>(node_feat, b1, b3);
    edge_kernel_mma<<<296, EDGE_THREADS, EDGE_SMEM_BYTES>>>(ea, eidx, E, NTE);
    node_fused_kernel<<<NBN, 256, PB_SMEM>>>(b4, out);
}

// round 15
// speedup vs baseline: 1.1269x; 1.0106x over previous
#include <cuda_runtime.h>
#include <cuda_bf16.h>
#include <cuda_fp16.h>
#include <cstdint>

#define N_NODES 50000
#define HID 128
#define EF 64

// ---------------------------------------------------------------------------
// Scratch (device globals — allocation-free per harness rules)
__device__ float g_P   [(size_t)N_NODES * HID];   // node_feat@W1_top+b1
__device__ float g_P3  [(size_t)N_NODES * HID];   // node_feat@W3_top+b3
__device__ float g_sums[(size_t)N_NODES * HID];   // scatter-add of relu-h
__device__ float g_cnt [N_NODES];
__device__ float g_W23 [128 * 128];               // W2 @ W3_bot (fp32)
__device__ float g_b23 [128];                     // b2 @ W3_bot
// Weight images, [N][K] K-major 128B rows, SW128-swizzled.
// [0,16K) B1 fp16 (edge)  |  [16K,32K) unused  |  then 4 node bf16 hi/lo
// images x 64KB each. widx: 0=W1_top 1=W3_top 2=W23 3=W4
__device__ __align__(16) unsigned char g_WB[32768 + 4 * 65536];

__device__ __forceinline__ uint32_t smem_u32(const void* p) {
    uint32_t a;
    asm("{ .reg .u64 t; cvta.to.shared.u64 t, %1; cvt.u32.u64 %0, t; }"
        : "=r"(a) : "l"(p));
    return a;
}
__device__ __forceinline__ uint32_t swz(uint32_t b) { return b ^ ((b >> 3) & 0x70); }

__device__ __forceinline__ void ldsm_x4(uint32_t* r, uint32_t addr) {
    asm volatile("ldmatrix.sync.aligned.m8n8.x4.shared.b16 {%0,%1,%2,%3}, [%4];"
                 : "=r"(r[0]), "=r"(r[1]), "=r"(r[2]), "=r"(r[3]) : "r"(addr));
}
__device__ __forceinline__ void mma_bf16(float* d, const uint32_t* a, const uint32_t* b) {
    asm volatile("mma.sync.aligned.m16n8k16.row.col.f32.bf16.bf16.f32 "
                 "{%0,%1,%2,%3}, {%4,%5,%6,%7}, {%8,%9}, {%0,%1,%2,%3};"
                 : "+f"(d[0]), "+f"(d[1]), "+f"(d[2]), "+f"(d[3])
                 : "r"(a[0]), "r"(a[1]), "r"(a[2]), "r"(a[3]), "r"(b[0]), "r"(b[1]));
}
__device__ __forceinline__ void mma_f16(float* d, const uint32_t* a, const uint32_t* b) {
    asm volatile("mma.sync.aligned.m16n8k16.row.col.f32.f16.f16.f32 "
                 "{%0,%1,%2,%3}, {%4,%5,%6,%7}, {%8,%9}, {%0,%1,%2,%3};"
                 : "+f"(d[0]), "+f"(d[1]), "+f"(d[2]), "+f"(d[3])
                 : "r"(a[0]), "r"(a[1]), "r"(a[2]), "r"(a[3]), "r"(b[0]), "r"(b[1]));
}
__device__ __forceinline__ uint32_t pack_bf16x2(float x, float y) {
    __nv_bfloat162 p = {__float2bfloat16(x), __float2bfloat16(y)};
    return *(uint32_t*)&p;
}
__device__ __forceinline__ void split2(float x, float y, uint32_t& hi, uint32_t& lo) {
    __nv_bfloat16 hx = __float2bfloat16(x), hy = __float2bfloat16(y);
    __nv_bfloat162 ph = {hx, hy};
    hi = *(uint32_t*)&ph;
    lo = pack_bf16x2(x - __bfloat162float(hx), y - __bfloat162float(hy));
}
__device__ __forceinline__ void split8(float4 v0, float4 v1, uint4& hi, uint4& lo) {
    split2(v0.x, v0.y, hi.x, lo.x);
    split2(v0.z, v0.w, hi.y, lo.y);
    split2(v1.x, v1.y, hi.z, lo.z);
    split2(v1.z, v1.w, hi.w, lo.w);
}
__device__ __forceinline__ uint32_t pack_h2(float x, float y) {
    __half2 p = __floats2half2_rn(x, y);
    return *(uint32_t*)&p;
}

// Shared K=128 bf16x3 GEMM core with x4 B-operand ldmatrix (256-thr kernels).
__device__ __forceinline__ void gemm128_core(
    uint32_t smb, uint32_t aoff, uint32_t woff, int lid,
    int arow, int akof, float acc[16][4]) {
    const int ntoff = lid >> 4;
    const int brow = lid & 7;
    const int bkof = ((lid >> 3) & 1) << 4;
    #pragma unroll
    for (int kt = 0; kt < 8; kt++) {
        const int chunk = (kt >> 2) * 16384;
        const int kb = (kt & 3) * 32;
        uint32_t ahi[4], alo[4];
        ldsm_x4(ahi, smb + aoff + chunk + swz(arow * 128 + kb + akof));
        ldsm_x4(alo, smb + aoff + 32768 + chunk + swz(arow * 128 + kb + akof));
        #pragma unroll
        for (int nt = 0; nt < 16; nt += 2) {
            uint32_t bo = swz(((nt + ntoff) * 8 + brow) * 128 + kb + bkof);
            uint32_t bh[4], bl[4];
            ldsm_x4(bh, smb + woff + chunk + bo);
            ldsm_x4(bl, smb + woff + 32768 + chunk + bo);
            mma_bf16(acc[nt],     ahi, bh);
            mma_bf16(acc[nt],     ahi, bl);
            mma_bf16(acc[nt],     alo, bh);
            mma_bf16(acc[nt + 1], ahi, bh + 2);
            mma_bf16(acc[nt + 1], ahi, bl + 2);
            mma_bf16(acc[nt + 1], alo, bh + 2);
        }
    }
}

// ---------------------------------------------------------------------------
__global__ void zero_kernel() {
    const size_t total4 = (size_t)N_NODES * HID / 4;
    float4* s = (float4*)g_sums;
    const float4 z = make_float4(0.f, 0.f, 0.f, 0.f);
    for (size_t i = (size_t)blockIdx.x * blockDim.x + threadIdx.x; i < total4;
         i += (size_t)gridDim.x * blockDim.x)
        s[i] = z;
    for (int i = blockIdx.x * blockDim.x + threadIdx.x; i < N_NODES;
         i += gridDim.x * blockDim.x)
        g_cnt[i] = 0.f;
}

// ---------------------------------------------------------------------------
// W23 = W2 @ W3[128:256], b23 = b2 @ W3[128:256]
__global__ void prep1_kernel(const float* __restrict__ W2,
                             const float* __restrict__ W3,
                             const float* __restrict__ b2) {
    __shared__ float srow[128];
    const int r = blockIdx.x;
    const int c = threadIdx.x;
    srow[c] = (r < 128) ? W2[r * 128 + c] : b2[c];
    __syncthreads();
    float acc = 0.f;
    #pragma unroll 4
    for (int k = 0; k < 128; k++)
        acc += srow[k] * W3[(128 + k) * 128 + c];
    if (r < 128) g_W23[r * 128 + c] = acc;
    else         g_b23[c] = acc;
}

// ---------------------------------------------------------------------------
__global__ void prep2_kernel(const float* __restrict__ W1,
                             const float* __restrict__ W3,
                             const float* __restrict__ W4) {
    const int tid = blockIdx.x * blockDim.x + threadIdx.x;
    const int nth = gridDim.x * blockDim.x;
    for (int i = tid; i < 128 * 64; i += nth) {   // edge B1 fp16 (single image)
        int n = i >> 6, k = i & 63;
        float v = W1[(128 + k) * 128 + n];
        uint32_t off = swz(n * 128 + k * 2);
        *(__half*)(g_WB + off) = __float2half(v);
    }
    for (int i = tid; i < 4 * 128 * 128; i += nth) {  // node weights (bf16 hi/lo)
        int widx = i >> 14, j = i & 16383;
        int n = j >> 7, k = j & 127;
        float v;
        if      (widx == 0) v = W1[k * 128 + n];
        else if (widx == 1) v = W3[k * 128 + n];
        else if (widx == 2) v = g_W23[k * 128 + n];
        else                v = W4[k * 128 + n];
        __nv_bfloat16 h = __float2bfloat16(v);
        __nv_bfloat16 l = __float2bfloat16(v - __bfloat162float(h));
        int c = k >> 6, kk = k & 63;
        uint32_t off = swz(n * 128 + kk * 2);
        unsigned char* base = g_WB + 32768 + widx * 65536;
        *(__nv_bfloat16*)(base + c * 16384 + off)         = h;
        *(__nv_bfloat16*)(base + 32768 + c * 16384 + off) = l;
    }
}

// ---------------------------------------------------------------------------
// pre_both: stage node_feat once; P = nf@W1t + b1; P3 = nf@W3t + b3.
#define PB_W 0
#define PB_A 65536
#define PB_BIAS 131072
#define PB_SMEM (131072 + 1024)

__global__ __launch_bounds__(256, 1)
void pre_both_kernel(const float* __restrict__ A, const float* __restrict__ b1,
                     const float* __restrict__ b3) {
    extern __shared__ char smc[];
    const uint32_t smb = smem_u32(smc);
    const int tid = threadIdx.x;
    const int wid = tid >> 5;
    const int lid = tid & 31;
    float* s_b1 = (float*)(smc + PB_BIAS);
    float* s_b3 = s_b1 + 128;

    {
        const float4* src = (const float4*)(g_WB + 32768);
        float4* dst = (float4*)smc;
        #pragma unroll
        for (int i = 0; i < 16; i++) dst[tid + 256 * i] = src[tid + 256 * i];
    }
    if (tid < 128) { s_b1[tid] = b1[tid]; s_b3[tid] = b3[tid]; }

    const int m0 = blockIdx.x * 128;
    {
        const int r = tid >> 1;
        const int chunk = tid & 1;
        const int gr = m0 + r;
        const bool valid = gr < N_NODES;
        const float* src = A + (size_t)gr * 128 + chunk * 64;
        #pragma unroll
        for (int j = 0; j < 8; j++) {
            float4 v0 = valid ? *(const float4*)(src + j * 8)
                              : make_float4(0.f, 0.f, 0.f, 0.f);
            float4 v1 = valid ? *(const float4*)(src + j * 8 + 4)
                              : make_float4(0.f, 0.f, 0.f, 0.f);
            uint4 hi, lo;
            split8(v0, v1, hi, lo);
            uint32_t off = swz(r * 128 + j * 16);
            *(uint4*)(smc + PB_A + chunk * 16384 + off) = hi;
            *(uint4*)(smc + PB_A + 32768 + chunk * 16384 + off) = lo;
        }
    }
    __syncthreads();

    const int wr0 = wid * 16;
    const int qr = lid >> 2, qc = (lid & 3) * 2;
    const int r0 = wr0 + qr, r1 = r0 + 8;
    const int am = lid >> 3;
    const int arow = wr0 + ((am & 1) << 3) + (lid & 7);
    const int akof = (am >> 1) << 4;
    const int gr0 = m0 + r0, gr1 = m0 + r1;

    float acc[16][4];
    #pragma unroll
    for (int nt = 0; nt < 16; nt++)
        #pragma unroll
        for (int v = 0; v < 4; v++) acc[nt][v] = 0.f;
    gemm128_core(smb, PB_A, PB_W, lid, arow, akof, acc);
    #pragma unroll
    for (int nt = 0; nt < 16; nt++) {
        const int c = nt * 8 + qc;
        if (gr0 < N_NODES)
            *(float2*)(g_P + (size_t)gr0 * 128 + c) = make_float2(
                acc[nt][0] + s_b1[c], acc[nt][1] + s_b1[c + 1]);
        if (gr1 < N_NODES)
            *(float2*)(g_P + (size_t)gr1 * 128 + c) = make_float2(
                acc[nt][2] + s_b1[c], acc[nt][3] + s_b1[c + 1]);
    }
    __syncthreads();
    {
        const float4* src = (const float4*)(g_WB + 32768 + 65536);
        float4* dst = (float4*)smc;
        #pragma unroll
        for (int i = 0; i < 16; i++) dst[tid + 256 * i] = src[tid + 256 * i];
    }
    __syncthreads();
    #pragma unroll
    for (int nt = 0; nt < 16; nt++)
        #pragma unroll
        for (int v = 0; v < 4; v++) acc[nt][v] = 0.f;
    gemm128_core(smb, PB_A, PB_W, lid, arow, akof, acc);
    #pragma unroll
    for (int nt = 0; nt < 16; nt++) {
        const int c = nt * 8 + qc;
        if (gr0 < N_NODES)
            *(float2*)(g_P3 + (size_t)gr0 * 128 + c) = make_float2(
                acc[nt][0] + s_b3[c], acc[nt][1] + s_b3[c + 1]);
        if (gr1 < N_NODES)
            *(float2*)(g_P3 + (size_t)gr1 * 128 + c) = make_float2(
                acc[nt][2] + s_b3[c], acc[nt][3] + s_b3[c + 1]);
    }
}

// ---------------------------------------------------------------------------
// node_fused: mean = sums/max(cnt,1); T = relu(P3 + mean@W23 + flag*b23);
// out = T@W4 + b4.
__global__ __launch_bounds__(256, 1)
void node_fused_kernel(const float* __restrict__ b4, float* __restrict__ out) {
    extern __shared__ char smc[];
    const uint32_t smb = smem_u32(smc);
    const int tid = threadIdx.x;
    const int wid = tid >> 5;
    const int lid = tid & 31;
    float* s_b23 = (float*)(smc + PB_BIAS);
    float* s_b4  = s_b23 + 128;

    {
        const float4* src = (const float4*)(g_WB + 32768 + 2 * 65536);
        float4* dst = (float4*)smc;
        #pragma unroll
        for (int i = 0; i < 16; i++) dst[tid + 256 * i] = src[tid + 256 * i];
    }
    if (tid < 128) { s_b23[tid] = g_b23[tid]; s_b4[tid] = b4[tid]; }

    const int m0 = blockIdx.x * 128;
    {
        const int r = tid >> 1;
        const int chunk = tid & 1;
        const int gr = m0 + r;
        const bool valid = gr < N_NODES;
        float s = valid ? 1.f / fmaxf(g_cnt[gr], 1.f) : 0.f;
        const float* src = g_sums + (size_t)gr * 128 + chunk * 64;
        #pragma unroll
        for (int j = 0; j < 8; j++) {
            float4 v0 = valid ? *(const float4*)(src + j * 8)
                              : make_float4(0.f, 0.f, 0.f, 0.f);
            float4 v1 = valid ? *(const float4*)(src + j * 8 + 4)
                              : make_float4(0.f, 0.f, 0.f, 0.f);
            v0.x *= s; v0.y *= s; v0.z *= s; v0.w *= s;
            v1.x *= s; v1.y *= s; v1.z *= s; v1.w *= s;
            uint4 hi, lo;
            split8(v0, v1, hi, lo);
            uint32_t off = swz(r * 128 + j * 16);
            *(uint4*)(smc + PB_A + chunk * 16384 + off) = hi;
            *(uint4*)(smc + PB_A + 32768 + chunk * 16384 + off) = lo;
        }
    }
    __syncthreads();

    const int wr0 = wid * 16;
    const int qr = lid >> 2, qc = (lid & 3) * 2;
    const int r0 = wr0 + qr, r1 = r0 + 8;
    const int am = lid >> 3;
    const int arow = wr0 + ((am & 1) << 3) + (lid & 7);
    const int akof = (am >> 1) << 4;
    const int gr0 = m0 + r0, gr1 = m0 + r1;

    float acc[16][4];
    #pragma unroll
    for (int nt = 0; nt < 16; nt++)
        #pragma unroll
        for (int v = 0; v < 4; v++) acc[nt][v] = 0.f;
    gemm128_core(smb, PB_A, PB_W, lid, arow, akof, acc);

    {
        const float f0 = (gr0 < N_NODES && g_cnt[gr0] > 0.f) ? 1.f : 0.f;
        const float f1 = (gr1 < N_NODES && g_cnt[gr1] > 0.f) ? 1.f : 0.f;
        #pragma unroll
        for (int nt = 0; nt < 16; nt++) {
            const int c = nt * 8 + qc;
            float t00 = 0.f, t01 = 0.f, t10 = 0.f, t11 = 0.f;
            if (gr0 < N_NODES) {
                float2 p = *(const float2*)(g_P3 + (size_t)gr0 * 128 + c);
                t00 = fmaxf(p.x + acc[nt][0] + f0 * s_b23[c], 0.f);
                t01 = fmaxf(p.y + acc[nt][1] + f0 * s_b23[c + 1], 0.f);
            }
            if (gr1 < N_NODES) {
                float2 p = *(const float2*)(g_P3 + (size_t)gr1 * 128 + c);
                t10 = fmaxf(p.x + acc[nt][2] + f1 * s_b23[c], 0.f);
                t11 = fmaxf(p.y + acc[nt][3] + f1 * s_b23[c + 1], 0.f);
            }
            uint32_t hi0, lo0, hi1, lo1;
            split2(t00, t01, hi0, lo0);
            split2(t10, t11, hi1, lo1);
            const int chunk = (c >> 6) * 16384;
            const int kk2 = (c & 63) * 2;
            *(uint32_t*)(smc + PB_A + chunk + swz(r0 * 128 + kk2)) = hi0;
            *(uint32_t*)(smc + PB_A + chunk + swz(r1 * 128 + kk2)) = hi1;
            *(uint32_t*)(smc + PB_A + 32768 + chunk + swz(r0 * 128 + kk2)) = lo0;
            *(uint32_t*)(smc + PB_A + 32768 + chunk + swz(r1 * 128 + kk2)) = lo1;
        }
    }
    __syncthreads();
    {
        const float4* src = (const float4*)(g_WB + 32768 + 3 * 65536);
        float4* dst = (float4*)smc;
        #pragma unroll
        for (int i = 0; i < 16; i++) dst[tid + 256 * i] = src[tid + 256 * i];
    }
    __syncthreads();
    #pragma unroll
    for (int nt = 0; nt < 16; nt++)
        #pragma unroll
        for (int v = 0; v < 4; v++) acc[nt][v] = 0.f;
    gemm128_core(smb, PB_A, PB_W, lid, arow, akof, acc);
    #pragma unroll
    for (int nt = 0; nt < 16; nt++) {
        const int c = nt * 8 + qc;
        if (gr0 < N_NODES)
            *(float2*)(out + (size_t)gr0 * 128 + c) = make_float2(
                acc[nt][0] + s_b4[c], acc[nt][1] + s_b4[c + 1]);
        if (gr1 < N_NODES)
            *(float2*)(out + (size_t)gr1 * 128 + c) = make_float2(
                acc[nt][2] + s_b4[c], acc[nt][3] + s_b4[c + 1]);
    }
}

// ---------------------------------------------------------------------------
// Edge kernel: 256 threads, 2 CTAs/SM, 64-edge tiles, SINGLE-TERM fp16:
// D1 = A(fp16) @ B1(fp16) — 1 MMA per fragment pair (was 2). Staging halves
// (no lo image). Error: A-quant 2^-11 joins B-quant 2^-11; measured transfer
// of the B term to final rel_err was ~1e-2x, so predicted rel_err ~2e-5.
// Double-buffered A staging, P prefetch, one __syncthreads per tile.
// SMEM: [0,16K) B1 fp16 | 16K A0(8K) | 24K A1(8K) | 32K idx (2 x 128 ints)
#define SM_B1   0
#define SM_A    16384
#define SM_IDX  32768
#define EDGE_SMEM_BYTES (32768 + 1280)
#define EDGE_THREADS 256
#define TILE_E 64

__global__ __launch_bounds__(EDGE_THREADS, 2)
void edge_kernel_mma(const float* __restrict__ ea, const int* __restrict__ eidx,
                     int E, int ntiles) {
    extern __shared__ char smc[];
    const uint32_t smb = smem_u32(smc);
    const int tid = threadIdx.x;
    const int wid = tid >> 5;
    const int lid = tid & 31;

    {   // B1 fp16 image once (16 KB)
        const float4* src = (const float4*)g_WB;
        float4* dst = (float4*)smc;
        for (int i = tid; i < 1024; i += EDGE_THREADS) dst[i] = src[i];
    }

    // staging lane geometry (4 threads/row, 16 floats each; 64 rows)
    const int st_r = tid >> 2;
    const int st_q = tid & 3;

    // MMA lane geometry: 4 row strips x 2 col halves
    const int rstrip = (wid >> 1) * 16;
    const int chalf  = (wid & 1) * 64;
    const int qr = lid >> 2;
    const int r0 = rstrip + qr, r1 = r0 + 8;
    const int am = lid >> 3;
    const int arow = rstrip + ((am & 1) << 3) + (lid & 7);
    const int akof = (am >> 1) << 4;
    const int ntoff = lid >> 4;
    const int brow = lid & 7;
    const int bkof = ((lid >> 3) & 1) << 4;
    // epilogue shuffle geometry
    const int cboff = (lid & 2) ? 4 : 0;
    const bool evenlane = ((lid & 1) == 0);
    const int myrow = evenlane ? r0 : r1;

    // ---- stage helper: 64-edge tile into buffer q (fp16, single image) ----
    auto stage = [&](int tile, int q) {
        const int e0s = tile * TILE_E;
        int* rowq = (int*)(smc + SM_IDX) + q * 128;
        int* colq = rowq + 64;
        if (tid < 64) {
            int e = e0s + tid;
            rowq[tid] = (e < E) ? eidx[e] : 0;
        } else if (tid < 128) {
            int t = tid - 64, e = e0s + t;
            colq[t] = (e < E) ? eidx[(size_t)E + e] : 0;
        }
        const int e = e0s + st_r;
        const bool valid = e < E;
        const float* src = ea + (size_t)e * EF + st_q * 16;
        const uint32_t abase = (uint32_t)(SM_A + q * 8192);
        #pragma unroll
        for (int j = 0; j < 2; j++) {
            float4 v0 = valid ? *(const float4*)(src + j * 8)
                              : make_float4(0.f, 0.f, 0.f, 0.f);
            float4 v1 = valid ? *(const float4*)(src + j * 8 + 4)
                              : make_float4(0.f, 0.f, 0.f, 0.f);
            uint4 hv;
            hv.x = pack_h2(v0.x, v0.y);
            hv.y = pack_h2(v0.z, v0.w);
            hv.z = pack_h2(v1.x, v1.y);
            hv.w = pack_h2(v1.z, v1.w);
            uint32_t off = swz(st_r * 128 + st_q * 32 + j * 16);
            *(uint4*)(smc + abase + off) = hv;
        }
    };

    if (blockIdx.x < ntiles) stage(blockIdx.x, 0);
    __syncthreads();

    int p = 0;
    for (int tile = blockIdx.x; tile < ntiles; tile += gridDim.x, p ^= 1) {
        const int e0 = tile * TILE_E;
        const int* rowp = (const int*)(smc + SM_IDX) + p * 128;
        const int* colp = rowp + 64;
        const uint32_t aoff = (uint32_t)(SM_A + p * 8192);

        // ---- prefetch this thread's P-row segment to L1 (overlaps GEMM) ----
        const int srcnode = colp[myrow];
        const float* Pbase = g_P + (size_t)srcnode * 128 + chalf;
        asm volatile("prefetch.global.L1 [%0];" :: "l"(Pbase));
        asm volatile("prefetch.global.L1 [%0];" :: "l"(Pbase + 32));

        // ---- GEMM1: 8 nt per warp; single fp16 MMA per pair element ----
        float acc[8][4];
        #pragma unroll
        for (int nt = 0; nt < 8; nt++)
            #pragma unroll
            for (int v = 0; v < 4; v++) acc[nt][v] = 0.f;
        #pragma unroll
        for (int kt = 0; kt < 4; kt++) {
            const int kb = kt * 32;
            uint32_t ah[4];
            ldsm_x4(ah, smb + aoff + swz(arow * 128 + kb + akof));
            #pragma unroll
            for (int nt = 0; nt < 8; nt += 2) {
                const int ntg = (chalf >> 3) + nt + ntoff;
                uint32_t bo = swz((ntg * 8 + brow) * 128 + kb + bkof);
                uint32_t bh[4];
                ldsm_x4(bh, smb + SM_B1 + bo);
                mma_f16(acc[nt],     ah, bh);
                mma_f16(acc[nt + 1], ah, bh + 2);
            }
        }

        // ---- stage NEXT tile into the other buffer (overlaps epilogue) ----
        const int nxt = tile + gridDim.x;
        if (nxt < ntiles) stage(nxt, 1 - p);

        // ---- epilogue: shuffle to float4; h = relu(D1 + P[col]); RED.F32X4
        {
            const bool valid = (e0 + myrow < E);
            const float* Pn = Pbase + cboff;
            float* Sn = g_sums + (size_t)rowp[myrow] * 128 + chalf + cboff;
            #pragma unroll
            for (int nt = 0; nt < 8; nt++) {
                float sA = evenlane ? acc[nt][2] : acc[nt][0];
                float sB = evenlane ? acc[nt][3] : acc[nt][1];
                float rA = __shfl_xor_sync(0xFFFFFFFFu, sA, 1);
                float rB = __shfl_xor_sync(0xFFFFFFFFu, sB, 1);
                float4 v = evenlane
                    ? make_float4(acc[nt][0], acc[nt][1], rA, rB)
                    : make_float4(rA, rB, acc[nt][2], acc[nt][3]);
                if (valid) {
                    float4 pv = *(const float4*)(Pn + nt * 8);
                    v.x = fmaxf(v.x + pv.x, 0.f);
                    v.y = fmaxf(v.y + pv.y, 0.f);
                    v.z = fmaxf(v.z + pv.z, 0.f);
                    v.w = fmaxf(v.w + pv.w, 0.f);
                    atomicAdd((float4*)(Sn + nt * 8), v);
                }
            }
        }
        if (tid < 64 && e0 + tid < E) atomicAdd(&g_cnt[rowp[tid]], 1.0f);

        __syncthreads();   // buffer 1-p fully staged; buffer p free to rewrite
    }
}

// ---------------------------------------------------------------------------
extern "C" void kernel_launch(void* const* d_in, const int* in_sizes, int n_in,
                              void* d_out, int out_size) {
    const float* node_feat = (const float*)d_in[0];
    const int*   eidx      = (const int*)d_in[1];   // int32 (JAX x64 disabled)
    const float* ea        = (const float*)d_in[2];
    const float* W1 = (const float*)d_in[3];
    const float* b1 = (const float*)d_in[4];
    const float* W2 = (const float*)d_in[5];
    const float* b2 = (const float*)d_in[6];
    const float* W3 = (const float*)d_in[7];
    const float* b3 = (const float*)d_in[8];
    const float* W4 = (const float*)d_in[9];
    const float* b4 = (const float*)d_in[10];
    float* out = (float*)d_out;

    const int E = in_sizes[1] / 2;
    const int NBN = (N_NODES + 127) / 128;      // 391
    const int NTE = (E + TILE_E - 1) / TILE_E;  // 25000

    cudaFuncSetAttribute(pre_both_kernel,
                         cudaFuncAttributeMaxDynamicSharedMemorySize, PB_SMEM);
    cudaFuncSetAttribute(node_fused_kernel,
                         cudaFuncAttributeMaxDynamicSharedMemorySize, PB_SMEM);
    cudaFuncSetAttribute(edge_kernel_mma,
                         cudaFuncAttributeMaxDynamicSharedMemorySize, EDGE_SMEM_BYTES);

    zero_kernel<<<1024, 256>>>();
    prep1_kernel<<<129, 128>>>(W2, W3, b2);
    prep2_kernel<<<64, 256>>>(W1, W3, W4);
    pre_both_kernel<<<NBN, 256, PB_SMEM>>>(node_feat, b1, b3);
    edge_kernel_mma<<<296, EDGE_THREADS, EDGE_SMEM_BYTES>>>(ea, eidx, E, NTE);
    node_fused_kernel<<<NBN, 256, PB_SMEM>>>(b4, out);
}

// round 16
// speedup vs baseline: 1.1735x; 1.0413x over previous
#include <cuda_runtime.h>
#include <cuda_bf16.h>
#include <cuda_fp16.h>
#include <cstdint>

#define N_NODES 50000
#define HID 128
#define EF 64

// ---------------------------------------------------------------------------
// Scratch (device globals — allocation-free per harness rules)
__device__ float g_P   [(size_t)N_NODES * HID];   // node_feat@W1_top+b1
__device__ float g_P3  [(size_t)N_NODES * HID];   // node_feat@W3_top+b3
__device__ float g_sums[(size_t)N_NODES * HID];   // scatter-add of relu-h
__device__ float g_cnt [N_NODES];
__device__ float g_W23 [128 * 128];               // W2 @ W3_bot (fp32)
__device__ float g_b23 [128];                     // b2 @ W3_bot
// Weight images, [N][K] K-major 128B rows, SW128-swizzled.
// [0,16K) B1 fp16 (edge) | [16K,32K) unused | then 4 node slots x 64KB:
//   widx 0=W1_top(fp16,32K used) 1=W3_top(fp16) 2=W23(fp16) 3=W4(bf16 hi/lo)
__device__ __align__(16) unsigned char g_WB[32768 + 4 * 65536];

__device__ __forceinline__ uint32_t smem_u32(const void* p) {
    uint32_t a;
    asm("{ .reg .u64 t; cvta.to.shared.u64 t, %1; cvt.u32.u64 %0, t; }"
        : "=r"(a) : "l"(p));
    return a;
}
__device__ __forceinline__ uint32_t swz(uint32_t b) { return b ^ ((b >> 3) & 0x70); }

__device__ __forceinline__ void ldsm_x4(uint32_t* r, uint32_t addr) {
    asm volatile("ldmatrix.sync.aligned.m8n8.x4.shared.b16 {%0,%1,%2,%3}, [%4];"
                 : "=r"(r[0]), "=r"(r[1]), "=r"(r[2]), "=r"(r[3]) : "r"(addr));
}
__device__ __forceinline__ void mma_bf16(float* d, const uint32_t* a, const uint32_t* b) {
    asm volatile("mma.sync.aligned.m16n8k16.row.col.f32.bf16.bf16.f32 "
                 "{%0,%1,%2,%3}, {%4,%5,%6,%7}, {%8,%9}, {%0,%1,%2,%3};"
                 : "+f"(d[0]), "+f"(d[1]), "+f"(d[2]), "+f"(d[3])
                 : "r"(a[0]), "r"(a[1]), "r"(a[2]), "r"(a[3]), "r"(b[0]), "r"(b[1]));
}
__device__ __forceinline__ void mma_f16(float* d, const uint32_t* a, const uint32_t* b) {
    asm volatile("mma.sync.aligned.m16n8k16.row.col.f32.f16.f16.f32 "
                 "{%0,%1,%2,%3}, {%4,%5,%6,%7}, {%8,%9}, {%0,%1,%2,%3};"
                 : "+f"(d[0]), "+f"(d[1]), "+f"(d[2]), "+f"(d[3])
                 : "r"(a[0]), "r"(a[1]), "r"(a[2]), "r"(a[3]), "r"(b[0]), "r"(b[1]));
}
__device__ __forceinline__ uint32_t pack_bf16x2(float x, float y) {
    __nv_bfloat162 p = {__float2bfloat16(x), __float2bfloat16(y)};
    return *(uint32_t*)&p;
}
__device__ __forceinline__ void split2(float x, float y, uint32_t& hi, uint32_t& lo) {
    __nv_bfloat16 hx = __float2bfloat16(x), hy = __float2bfloat16(y);
    __nv_bfloat162 ph = {hx, hy};
    hi = *(uint32_t*)&ph;
    lo = pack_bf16x2(x - __bfloat162float(hx), y - __bfloat162float(hy));
}
__device__ __forceinline__ uint32_t pack_h2(float x, float y) {
    __half2 p = __floats2half2_rn(x, y);
    return *(uint32_t*)&p;
}

// K=128 bf16x3 GEMM core (A hi/lo at aoff, aoff+32768; W same layout).
__device__ __forceinline__ void gemm128_core(
    uint32_t smb, uint32_t aoff, uint32_t woff, int lid,
    int arow, int akof, float acc[16][4]) {
    const int ntoff = lid >> 4;
    const int brow = lid & 7;
    const int bkof = ((lid >> 3) & 1) << 4;
    #pragma unroll
    for (int kt = 0; kt < 8; kt++) {
        const int chunk = (kt >> 2) * 16384;
        const int kb = (kt & 3) * 32;
        uint32_t ahi[4], alo[4];
        ldsm_x4(ahi, smb + aoff + chunk + swz(arow * 128 + kb + akof));
        ldsm_x4(alo, smb + aoff + 32768 + chunk + swz(arow * 128 + kb + akof));
        #pragma unroll
        for (int nt = 0; nt < 16; nt += 2) {
            uint32_t bo = swz(((nt + ntoff) * 8 + brow) * 128 + kb + bkof);
            uint32_t bh[4], bl[4];
            ldsm_x4(bh, smb + woff + chunk + bo);
            ldsm_x4(bl, smb + woff + 32768 + chunk + bo);
            mma_bf16(acc[nt],     ahi, bh);
            mma_bf16(acc[nt],     ahi, bl);
            mma_bf16(acc[nt],     alo, bh);
            mma_bf16(acc[nt + 1], ahi, bh + 2);
            mma_bf16(acc[nt + 1], ahi, bl + 2);
            mma_bf16(acc[nt + 1], alo, bh + 2);
        }
    }
}

// K=128 fp16 single-term GEMM core (A at aoff, 2 chunks x 16K; W same).
__device__ __forceinline__ void gemm128_f16_core(
    uint32_t smb, uint32_t aoff, uint32_t woff, int lid,
    int arow, int akof, float acc[16][4]) {
    const int ntoff = lid >> 4;
    const int brow = lid & 7;
    const int bkof = ((lid >> 3) & 1) << 4;
    #pragma unroll
    for (int kt = 0; kt < 8; kt++) {
        const int chunk = (kt >> 2) * 16384;
        const int kb = (kt & 3) * 32;
        uint32_t ah[4];
        ldsm_x4(ah, smb + aoff + chunk + swz(arow * 128 + kb + akof));
        #pragma unroll
        for (int nt = 0; nt < 16; nt += 2) {
            uint32_t bo = swz(((nt + ntoff) * 8 + brow) * 128 + kb + bkof);
            uint32_t bh[4];
            ldsm_x4(bh, smb + woff + chunk + bo);
            mma_f16(acc[nt],     ah, bh);
            mma_f16(acc[nt + 1], ah, bh + 2);
        }
    }
}

// ---------------------------------------------------------------------------
__global__ void zero_kernel() {
    const size_t total4 = (size_t)N_NODES * HID / 4;
    float4* s = (float4*)g_sums;
    const float4 z = make_float4(0.f, 0.f, 0.f, 0.f);
    for (size_t i = (size_t)blockIdx.x * blockDim.x + threadIdx.x; i < total4;
         i += (size_t)gridDim.x * blockDim.x)
        s[i] = z;
    for (int i = blockIdx.x * blockDim.x + threadIdx.x; i < N_NODES;
         i += gridDim.x * blockDim.x)
        g_cnt[i] = 0.f;
}

// ---------------------------------------------------------------------------
// W23 = W2 @ W3[128:256], b23 = b2 @ W3[128:256]
__global__ void prep1_kernel(const float* __restrict__ W2,
                             const float* __restrict__ W3,
                             const float* __restrict__ b2) {
    __shared__ float srow[128];
    const int r = blockIdx.x;
    const int c = threadIdx.x;
    srow[c] = (r < 128) ? W2[r * 128 + c] : b2[c];
    __syncthreads();
    float acc = 0.f;
    #pragma unroll 4
    for (int k = 0; k < 128; k++)
        acc += srow[k] * W3[(128 + k) * 128 + c];
    if (r < 128) g_W23[r * 128 + c] = acc;
    else         g_b23[c] = acc;
}

// ---------------------------------------------------------------------------
__global__ void prep2_kernel(const float* __restrict__ W1,
                             const float* __restrict__ W3,
                             const float* __restrict__ W4) {
    const int tid = blockIdx.x * blockDim.x + threadIdx.x;
    const int nth = gridDim.x * blockDim.x;
    for (int i = tid; i < 128 * 64; i += nth) {   // edge B1 fp16
        int n = i >> 6, k = i & 63;
        float v = W1[(128 + k) * 128 + n];
        uint32_t off = swz(n * 128 + k * 2);
        *(__half*)(g_WB + off) = __float2half(v);
    }
    for (int i = tid; i < 4 * 128 * 128; i += nth) {  // node weights
        int widx = i >> 14, j = i & 16383;
        int n = j >> 7, k = j & 127;
        float v;
        if      (widx == 0) v = W1[k * 128 + n];
        else if (widx == 1) v = W3[k * 128 + n];
        else if (widx == 2) v = g_W23[k * 128 + n];
        else                v = W4[k * 128 + n];
        int c = k >> 6, kk = k & 63;
        uint32_t off = swz(n * 128 + kk * 2);
        unsigned char* base = g_WB + 32768 + widx * 65536;
        if (widx < 3) {   // fp16 single image (2 chunks x 16KB)
            *(__half*)(base + c * 16384 + off) = __float2half(v);
        } else {          // W4: bf16 hi/lo
            __nv_bfloat16 h = __float2bfloat16(v);
            __nv_bfloat16 l = __float2bfloat16(v - __bfloat162float(h));
            *(__nv_bfloat16*)(base + c * 16384 + off)         = h;
            *(__nv_bfloat16*)(base + 32768 + c * 16384 + off) = l;
        }
    }
}

// ---------------------------------------------------------------------------
// pre_both: stage node_feat once (fp16); P = nf@W1t + b1; P3 = nf@W3t + b3.
// Both GEMMs fp16 single-term.
#define PB_W 0
#define PB_A 65536
#define PB_BIAS 131072
#define PB_SMEM (131072 + 1024)

__global__ __launch_bounds__(256, 1)
void pre_both_kernel(const float* __restrict__ A, const float* __restrict__ b1,
                     const float* __restrict__ b3) {
    extern __shared__ char smc[];
    const uint32_t smb = smem_u32(smc);
    const int tid = threadIdx.x;
    const int wid = tid >> 5;
    const int lid = tid & 31;
    float* s_b1 = (float*)(smc + PB_BIAS);
    float* s_b3 = s_b1 + 128;

    {   // W1_top fp16 image (32 KB)
        const float4* src = (const float4*)(g_WB + 32768);
        float4* dst = (float4*)smc;
        #pragma unroll
        for (int i = 0; i < 8; i++) dst[tid + 256 * i] = src[tid + 256 * i];
    }
    if (tid < 128) { s_b1[tid] = b1[tid]; s_b3[tid] = b3[tid]; }

    const int m0 = blockIdx.x * 128;
    {   // stage node_feat -> fp16 single image
        const int r = tid >> 1;
        const int chunk = tid & 1;
        const int gr = m0 + r;
        const bool valid = gr < N_NODES;
        const float* src = A + (size_t)gr * 128 + chunk * 64;
        #pragma unroll
        for (int j = 0; j < 8; j++) {
            float4 v0 = valid ? *(const float4*)(src + j * 8)
                              : make_float4(0.f, 0.f, 0.f, 0.f);
            float4 v1 = valid ? *(const float4*)(src + j * 8 + 4)
                              : make_float4(0.f, 0.f, 0.f, 0.f);
            uint4 hv;
            hv.x = pack_h2(v0.x, v0.y);
            hv.y = pack_h2(v0.z, v0.w);
            hv.z = pack_h2(v1.x, v1.y);
            hv.w = pack_h2(v1.z, v1.w);
            uint32_t off = swz(r * 128 + j * 16);
            *(uint4*)(smc + PB_A + chunk * 16384 + off) = hv;
        }
    }
    __syncthreads();

    const int wr0 = wid * 16;
    const int qr = lid >> 2, qc = (lid & 3) * 2;
    const int r0 = wr0 + qr, r1 = r0 + 8;
    const int am = lid >> 3;
    const int arow = wr0 + ((am & 1) << 3) + (lid & 7);
    const int akof = (am >> 1) << 4;
    const int gr0 = m0 + r0, gr1 = m0 + r1;

    float acc[16][4];
    #pragma unroll
    for (int nt = 0; nt < 16; nt++)
        #pragma unroll
        for (int v = 0; v < 4; v++) acc[nt][v] = 0.f;
    gemm128_f16_core(smb, PB_A, PB_W, lid, arow, akof, acc);
    #pragma unroll
    for (int nt = 0; nt < 16; nt++) {
        const int c = nt * 8 + qc;
        if (gr0 < N_NODES)
            *(float2*)(g_P + (size_t)gr0 * 128 + c) = make_float2(
                acc[nt][0] + s_b1[c], acc[nt][1] + s_b1[c + 1]);
        if (gr1 < N_NODES)
            *(float2*)(g_P + (size_t)gr1 * 128 + c) = make_float2(
                acc[nt][2] + s_b1[c], acc[nt][3] + s_b1[c + 1]);
    }
    __syncthreads();
    {   // swap to W3_top fp16 image
        const float4* src = (const float4*)(g_WB + 32768 + 65536);
        float4* dst = (float4*)smc;
        #pragma unroll
        for (int i = 0; i < 8; i++) dst[tid + 256 * i] = src[tid + 256 * i];
    }
    __syncthreads();
    #pragma unroll
    for (int nt = 0; nt < 16; nt++)
        #pragma unroll
        for (int v = 0; v < 4; v++) acc[nt][v] = 0.f;
    gemm128_f16_core(smb, PB_A, PB_W, lid, arow, akof, acc);
    #pragma unroll
    for (int nt = 0; nt < 16; nt++) {
        const int c = nt * 8 + qc;
        if (gr0 < N_NODES)
            *(float2*)(g_P3 + (size_t)gr0 * 128 + c) = make_float2(
                acc[nt][0] + s_b3[c], acc[nt][1] + s_b3[c + 1]);
        if (gr1 < N_NODES)
            *(float2*)(g_P3 + (size_t)gr1 * 128 + c) = make_float2(
                acc[nt][2] + s_b3[c], acc[nt][3] + s_b3[c + 1]);
    }
}

// ---------------------------------------------------------------------------
// node_fused: mean = sums/max(cnt,1); T = relu(P3 + mean@W23 + flag*b23)
// [fp16 GEMM]; out = T@W4 + b4 [bf16x3 — final output, full precision].
__global__ __launch_bounds__(256, 1)
void node_fused_kernel(const float* __restrict__ b4, float* __restrict__ out) {
    extern __shared__ char smc[];
    const uint32_t smb = smem_u32(smc);
    const int tid = threadIdx.x;
    const int wid = tid >> 5;
    const int lid = tid & 31;
    float* s_b23 = (float*)(smc + PB_BIAS);
    float* s_b4  = s_b23 + 128;

    {   // W23 fp16 image (32 KB)
        const float4* src = (const float4*)(g_WB + 32768 + 2 * 65536);
        float4* dst = (float4*)smc;
        #pragma unroll
        for (int i = 0; i < 8; i++) dst[tid + 256 * i] = src[tid + 256 * i];
    }
    if (tid < 128) { s_b23[tid] = g_b23[tid]; s_b4[tid] = b4[tid]; }

    const int m0 = blockIdx.x * 128;
    {   // stage mean -> fp16 single image
        const int r = tid >> 1;
        const int chunk = tid & 1;
        const int gr = m0 + r;
        const bool valid = gr < N_NODES;
        float s = valid ? 1.f / fmaxf(g_cnt[gr], 1.f) : 0.f;
        const float* src = g_sums + (size_t)gr * 128 + chunk * 64;
        #pragma unroll
        for (int j = 0; j < 8; j++) {
            float4 v0 = valid ? *(const float4*)(src + j * 8)
                              : make_float4(0.f, 0.f, 0.f, 0.f);
            float4 v1 = valid ? *(const float4*)(src + j * 8 + 4)
                              : make_float4(0.f, 0.f, 0.f, 0.f);
            v0.x *= s; v0.y *= s; v0.z *= s; v0.w *= s;
            v1.x *= s; v1.y *= s; v1.z *= s; v1.w *= s;
            uint4 hv;
            hv.x = pack_h2(v0.x, v0.y);
            hv.y = pack_h2(v0.z, v0.w);
            hv.z = pack_h2(v1.x, v1.y);
            hv.w = pack_h2(v1.z, v1.w);
            uint32_t off = swz(r * 128 + j * 16);
            *(uint4*)(smc + PB_A + chunk * 16384 + off) = hv;
        }
    }
    __syncthreads();

    const int wr0 = wid * 16;
    const int qr = lid >> 2, qc = (lid & 3) * 2;
    const int r0 = wr0 + qr, r1 = r0 + 8;
    const int am = lid >> 3;
    const int arow = wr0 + ((am & 1) << 3) + (lid & 7);
    const int akof = (am >> 1) << 4;
    const int gr0 = m0 + r0, gr1 = m0 + r1;

    float acc[16][4];
    #pragma unroll
    for (int nt = 0; nt < 16; nt++)
        #pragma unroll
        for (int v = 0; v < 4; v++) acc[nt][v] = 0.f;
    gemm128_f16_core(smb, PB_A, PB_W, lid, arow, akof, acc);

    // T = relu(P3 + acc + flag*b23) -> restage as bf16 hi/lo (own warp strip)
    {
        const float f0 = (gr0 < N_NODES && g_cnt[gr0] > 0.f) ? 1.f : 0.f;
        const float f1 = (gr1 < N_NODES && g_cnt[gr1] > 0.f) ? 1.f : 0.f;
        #pragma unroll
        for (int nt = 0; nt < 16; nt++) {
            const int c = nt * 8 + qc;
            float t00 = 0.f, t01 = 0.f, t10 = 0.f, t11 = 0.f;
            if (gr0 < N_NODES) {
                float2 p = *(const float2*)(g_P3 + (size_t)gr0 * 128 + c);
                t00 = fmaxf(p.x + acc[nt][0] + f0 * s_b23[c], 0.f);
                t01 = fmaxf(p.y + acc[nt][1] + f0 * s_b23[c + 1], 0.f);
            }
            if (gr1 < N_NODES) {
                float2 p = *(const float2*)(g_P3 + (size_t)gr1 * 128 + c);
                t10 = fmaxf(p.x + acc[nt][2] + f1 * s_b23[c], 0.f);
                t11 = fmaxf(p.y + acc[nt][3] + f1 * s_b23[c + 1], 0.f);
            }
            uint32_t hi0, lo0, hi1, lo1;
            split2(t00, t01, hi0, lo0);
            split2(t10, t11, hi1, lo1);
            const int chunk = (c >> 6) * 16384;
            const int kk2 = (c & 63) * 2;
            *(uint32_t*)(smc + PB_A + chunk + swz(r0 * 128 + kk2)) = hi0;
            *(uint32_t*)(smc + PB_A + chunk + swz(r1 * 128 + kk2)) = hi1;
            *(uint32_t*)(smc + PB_A + 32768 + chunk + swz(r0 * 128 + kk2)) = lo0;
            *(uint32_t*)(smc + PB_A + 32768 + chunk + swz(r1 * 128 + kk2)) = lo1;
        }
    }
    __syncthreads();
    {   // swap to W4 bf16 hi/lo image (64 KB)
        const float4* src = (const float4*)(g_WB + 32768 + 3 * 65536);
        float4* dst = (float4*)smc;
        #pragma unroll
        for (int i = 0; i < 16; i++) dst[tid + 256 * i] = src[tid + 256 * i];
    }
    __syncthreads();
    #pragma unroll
    for (int nt = 0; nt < 16; nt++)
        #pragma unroll
        for (int v = 0; v < 4; v++) acc[nt][v] = 0.f;
    gemm128_core(smb, PB_A, PB_W, lid, arow, akof, acc);
    #pragma unroll
    for (int nt = 0; nt < 16; nt++) {
        const int c = nt * 8 + qc;
        if (gr0 < N_NODES)
            *(float2*)(out + (size_t)gr0 * 128 + c) = make_float2(
                acc[nt][0] + s_b4[c], acc[nt][1] + s_b4[c + 1]);
        if (gr1 < N_NODES)
            *(float2*)(out + (size_t)gr1 * 128 + c) = make_float2(
                acc[nt][2] + s_b4[c], acc[nt][3] + s_b4[c + 1]);
    }
}

// ---------------------------------------------------------------------------
// Edge kernel (unchanged from R15): 256 threads, 2 CTAs/SM, 64-edge tiles,
// single-term fp16 D1 = A@B1; scatter relu(D1 + P[col]) via float4 REDs.
#define SM_B1   0
#define SM_A    16384
#define SM_IDX  32768
#define EDGE_SMEM_BYTES (32768 + 1280)
#define EDGE_THREADS 256
#define TILE_E 64

__global__ __launch_bounds__(EDGE_THREADS, 2)
void edge_kernel_mma(const float* __restrict__ ea, const int* __restrict__ eidx,
                     int E, int ntiles) {
    extern __shared__ char smc[];
    const uint32_t smb = smem_u32(smc);
    const int tid = threadIdx.x;
    const int wid = tid >> 5;
    const int lid = tid & 31;

    {   // B1 fp16 image once (16 KB)
        const float4* src = (const float4*)g_WB;
        float4* dst = (float4*)smc;
        for (int i = tid; i < 1024; i += EDGE_THREADS) dst[i] = src[i];
    }

    const int st_r = tid >> 2;
    const int st_q = tid & 3;

    const int rstrip = (wid >> 1) * 16;
    const int chalf  = (wid & 1) * 64;
    const int qr = lid >> 2;
    const int r0 = rstrip + qr, r1 = r0 + 8;
    const int am = lid >> 3;
    const int arow = rstrip + ((am & 1) << 3) + (lid & 7);
    const int akof = (am >> 1) << 4;
    const int ntoff = lid >> 4;
    const int brow = lid & 7;
    const int bkof = ((lid >> 3) & 1) << 4;
    const int cboff = (lid & 2) ? 4 : 0;
    const bool evenlane = ((lid & 1) == 0);
    const int myrow = evenlane ? r0 : r1;

    auto stage = [&](int tile, int q) {
        const int e0s = tile * TILE_E;
        int* rowq = (int*)(smc + SM_IDX) + q * 128;
        int* colq = rowq + 64;
        if (tid < 64) {
            int e = e0s + tid;
            rowq[tid] = (e < E) ? eidx[e] : 0;
        } else if (tid < 128) {
            int t = tid - 64, e = e0s + t;
            colq[t] = (e < E) ? eidx[(size_t)E + e] : 0;
        }
        const int e = e0s + st_r;
        const bool valid = e < E;
        const float* src = ea + (size_t)e * EF + st_q * 16;
        const uint32_t abase = (uint32_t)(SM_A + q * 8192);
        #pragma unroll
        for (int j = 0; j < 2; j++) {
            float4 v0 = valid ? *(const float4*)(src + j * 8)
                              : make_float4(0.f, 0.f, 0.f, 0.f);
            float4 v1 = valid ? *(const float4*)(src + j * 8 + 4)
                              : make_float4(0.f, 0.f, 0.f, 0.f);
            uint4 hv;
            hv.x = pack_h2(v0.x, v0.y);
            hv.y = pack_h2(v0.z, v0.w);
            hv.z = pack_h2(v1.x, v1.y);
            hv.w = pack_h2(v1.z, v1.w);
            uint32_t off = swz(st_r * 128 + st_q * 32 + j * 16);
            *(uint4*)(smc + abase + off) = hv;
        }
    };

    if (blockIdx.x < ntiles) stage(blockIdx.x, 0);
    __syncthreads();

    int p = 0;
    for (int tile = blockIdx.x; tile < ntiles; tile += gridDim.x, p ^= 1) {
        const int e0 = tile * TILE_E;
        const int* rowp = (const int*)(smc + SM_IDX) + p * 128;
        const int* colp = rowp + 64;
        const uint32_t aoff = (uint32_t)(SM_A + p * 8192);

        const int srcnode = colp[myrow];
        const float* Pbase = g_P + (size_t)srcnode * 128 + chalf;
        asm volatile("prefetch.global.L1 [%0];" :: "l"(Pbase));
        asm volatile("prefetch.global.L1 [%0];" :: "l"(Pbase + 32));

        float acc[8][4];
        #pragma unroll
        for (int nt = 0; nt < 8; nt++)
            #pragma unroll
            for (int v = 0; v < 4; v++) acc[nt][v] = 0.f;
        #pragma unroll
        for (int kt = 0; kt < 4; kt++) {
            const int kb = kt * 32;
            uint32_t ah[4];
            ldsm_x4(ah, smb + aoff + swz(arow * 128 + kb + akof));
            #pragma unroll
            for (int nt = 0; nt < 8; nt += 2) {
                const int ntg = (chalf >> 3) + nt + ntoff;
                uint32_t bo = swz((ntg * 8 + brow) * 128 + kb + bkof);
                uint32_t bh[4];
                ldsm_x4(bh, smb + SM_B1 + bo);
                mma_f16(acc[nt],     ah, bh);
                mma_f16(acc[nt + 1], ah, bh + 2);
            }
        }

        const int nxt = tile + gridDim.x;
        if (nxt < ntiles) stage(nxt, 1 - p);

        {
            const bool valid = (e0 + myrow < E);
            const float* Pn = Pbase + cboff;
            float* Sn = g_sums + (size_t)rowp[myrow] * 128 + chalf + cboff;
            #pragma unroll
            for (int nt = 0; nt < 8; nt++) {
                float sA = evenlane ? acc[nt][2] : acc[nt][0];
                float sB = evenlane ? acc[nt][3] : acc[nt][1];
                float rA = __shfl_xor_sync(0xFFFFFFFFu, sA, 1);
                float rB = __shfl_xor_sync(0xFFFFFFFFu, sB, 1);
                float4 v = evenlane
                    ? make_float4(acc[nt][0], acc[nt][1], rA, rB)
                    : make_float4(rA, rB, acc[nt][2], acc[nt][3]);
                if (valid) {
                    float4 pv = *(const float4*)(Pn + nt * 8);
                    v.x = fmaxf(v.x + pv.x, 0.f);
                    v.y = fmaxf(v.y + pv.y, 0.f);
                    v.z = fmaxf(v.z + pv.z, 0.f);
                    v.w = fmaxf(v.w + pv.w, 0.f);
                    atomicAdd((float4*)(Sn + nt * 8), v);
                }
            }
        }
        if (tid < 64 && e0 + tid < E) atomicAdd(&g_cnt[rowp[tid]], 1.0f);

        __syncthreads();
    }
}

// ---------------------------------------------------------------------------
extern "C" void kernel_launch(void* const* d_in, const int* in_sizes, int n_in,
                              void* d_out, int out_size) {
    const float* node_feat = (const float*)d_in[0];
    const int*   eidx      = (const int*)d_in[1];   // int32 (JAX x64 disabled)
    const float* ea        = (const float*)d_in[2];
    const float* W1 = (const float*)d_in[3];
    const float* b1 = (const float*)d_in[4];
    const float* W2 = (const float*)d_in[5];
    const float* b2 = (const float*)d_in[6];
    const float* W3 = (const float*)d_in[7];
    const float* b3 = (const float*)d_in[8];
    const float* W4 = (const float*)d_in[9];
    const float* b4 = (const float*)d_in[10];
    float* out = (float*)d_out;

    const int E = in_sizes[1] / 2;
    const int NBN = (N_NODES + 127) / 128;      // 391
    const int NTE = (E + TILE_E - 1) / TILE_E;  // 25000

    cudaFuncSetAttribute(pre_both_kernel,
                         cudaFuncAttributeMaxDynamicSharedMemorySize, PB_SMEM);
    cudaFuncSetAttribute(node_fused_kernel,
                         cudaFuncAttributeMaxDynamicSharedMemorySize, PB_SMEM);
    cudaFuncSetAttribute(edge_kernel_mma,
                         cudaFuncAttributeMaxDynamicSharedMemorySize, EDGE_SMEM_BYTES);

    zero_kernel<<<1024, 256>>>();
    prep1_kernel<<<129, 128>>>(W2, W3, b2);
    prep2_kernel<<<64, 256>>>(W1, W3, W4);
    pre_both_kernel<<<NBN, 256, PB_SMEM>>>(node_feat, b1, b3);
    edge_kernel_mma<<<296, EDGE_THREADS, EDGE_SMEM_BYTES>>>(ea, eidx, E, NTE);
    node_fused_kernel<<<NBN, 256, PB_SMEM>>>(b4, out);
}